// round 11
// baseline (speedup 1.0000x reference)
#include <cuda_runtime.h>

// ---------------------------------------------------------------------------
// Fused MHA block (mma.sync only — tcgen05 unavailable at .target sm_100):
//   QKV GEMM  : bf16 m16n8k16 3-term split + ldmatrix  [NEW]
//   attention : S bf16 3-term + register-P PV bf16 3-term (R10 proven)
//   proj GEMM : bf16 m16n8k16 3-term split + ldmatrix  [NEW]
// Shapes: B=2, N=2048, EMBED=1024, HEADS=16, HDIM=64.
// ---------------------------------------------------------------------------

#define BATCH  2
#define SEQ    2048
#define EMBED  1024
#define HEADS  16
#define HDIM   64
#define MTOK   (BATCH * SEQ)      // 4096
#define QKVN   (3 * EMBED)        // 3072
#define SCALE  0.125f             // HDIM^-0.5

__device__ float g_Q[BATCH * HEADS * SEQ * HDIM];   // [B,H,N,Dh]
__device__ float g_K[BATCH * HEADS * SEQ * HDIM];
__device__ float g_V[BATCH * HEADS * SEQ * HDIM];
__device__ float g_O[BATCH * SEQ * EMBED];          // attention output [B,N,EMBED]

// ------------------------------- helpers -----------------------------------
// Pack two floats into bf16x2: f0 -> low half, f1 -> high half.
__device__ __forceinline__ unsigned pk_bf(float f0, float f1) {
    unsigned d;
    asm("cvt.rn.bf16x2.f32 %0, %1, %2;" : "=r"(d) : "f"(f1), "f"(f0));
    return d;
}
// Split a float pair into bf16 hi-pair + residual lo-pair.
__device__ __forceinline__ void bfsplit2(float f0, float f1, unsigned& hi, unsigned& lo) {
    hi = pk_bf(f0, f1);
    float e0 = __uint_as_float(hi << 16);
    float e1 = __uint_as_float(hi & 0xffff0000u);
    lo = pk_bf(f0 - e0, f1 - e1);
}
__device__ __forceinline__ void mma_bf16(float* c, const unsigned* a, const unsigned* b) {
    asm volatile(
        "mma.sync.aligned.m16n8k16.row.col.f32.bf16.bf16.f32 "
        "{%0,%1,%2,%3}, {%4,%5,%6,%7}, {%8,%9}, {%0,%1,%2,%3};\n"
        : "+f"(c[0]), "+f"(c[1]), "+f"(c[2]), "+f"(c[3])
        : "r"(a[0]), "r"(a[1]), "r"(a[2]), "r"(a[3]),
          "r"(b[0]), "r"(b[1]));
}
__device__ __forceinline__ void ldsm_x4(unsigned& r0, unsigned& r1,
                                        unsigned& r2, unsigned& r3, unsigned addr) {
    asm volatile("ldmatrix.sync.aligned.m8n8.x4.shared.b16 {%0,%1,%2,%3}, [%4];"
                 : "=r"(r0), "=r"(r1), "=r"(r2), "=r"(r3) : "r"(addr));
}
__device__ __forceinline__ void ldsm_x4t(unsigned& r0, unsigned& r1,
                                         unsigned& r2, unsigned& r3, unsigned addr) {
    asm volatile("ldmatrix.sync.aligned.m8n8.x4.trans.shared.b16 {%0,%1,%2,%3}, [%4];"
                 : "=r"(r0), "=r"(r1), "=r"(r2), "=r"(r3) : "r"(addr));
}
__device__ __forceinline__ unsigned smem_u32(const void* p) {
    return (unsigned)__cvta_generic_to_shared(p);
}

// ---------------------------------------------------------------------------
// GEMM: C[M,N] = A[M,K] @ W[N,K]^T + bias[N]
// bf16 m16n8k16, 3-term split (AhBh + AhBl + AlBh), ldmatrix fragments.
// 128x128 tile, BK=32, 256 threads = 8 warps (4M x 2N), warp tile 32x64.
// Smem: AH/AL/BH/BL, each 128 rows x 80B stride (64B data + 16B pad).
// Stride 80B: ldsm 8-row phases hit banks r*20 mod 32 = {0,20,8,28,16,4,24,12}
// (all distinct quads) — conflict-free.
// ---------------------------------------------------------------------------
#define GAH 0
#define GAL 10240
#define GBH 20480
#define GBL 30720

template <int MODE>
__global__ __launch_bounds__(256)
void gemm_bf(const float* __restrict__ A, const float* __restrict__ W,
             const float* __restrict__ bias, float* __restrict__ out,
             int M, int N, int K)
{
    __shared__ char smc[4 * 128 * 80];
    const unsigned sbase = smem_u32(smc);

    const int tid  = threadIdx.x;
    const int wid  = tid >> 5;
    const int lane = tid & 31;
    const int g    = lane >> 2;
    const int t    = lane & 3;

    const int wm0 = (wid & 3) * 32;
    const int wn0 = (wid >> 2) * 64;

    const int m0 = blockIdx.y * 128;
    const int n0 = blockIdx.x * 128;

    float acc[2][8][4];
#pragma unroll
    for (int mi = 0; mi < 2; ++mi)
#pragma unroll
        for (int nj = 0; nj < 8; ++nj)
#pragma unroll
            for (int r = 0; r < 4; ++r) acc[mi][nj][r] = 0.f;

    // ldmatrix lane address components.
    const int a_rsub = lane & 15;              // A-frag row-in-16
    const int a_ko   = (lane >> 4) << 3;       // A-frag k-offset
    const int b_rs   = ((lane >> 4) << 3) + (lane & 7);  // B-frag row-in-16
    const int b_ko   = ((lane >> 3) & 1) << 3;           // B-frag k-offset

    for (int k0 = 0; k0 < K; k0 += 32) {
        // Stage: A tile 128x32 + B tile 128x32 -> bf16 hi/lo (8 f4/thread).
#pragma unroll
        for (int i = 0; i < 8; ++i) {
            const int idx = tid + 256 * i;         // 0..2047
            const int f   = idx & 1023;
            const int row = f >> 3;                // 0..127
            const int c4  = (f & 7) * 4;           // 0..28
            const float* src = (idx < 1024) ? &A[(size_t)(m0 + row) * K + k0 + c4]
                                            : &W[(size_t)(n0 + row) * K + k0 + c4];
            float4 v = *(const float4*)src;
            unsigned h01, l01, h23, l23;
            bfsplit2(v.x, v.y, h01, l01);
            bfsplit2(v.z, v.w, h23, l23);
            const int bo = row * 80 + c4 * 2;
            const int hiT = (idx < 1024) ? GAH : GBH;
            const int loT = (idx < 1024) ? GAL : GBL;
            *(uint2*)(smc + hiT + bo) = make_uint2(h01, h23);
            *(uint2*)(smc + loT + bo) = make_uint2(l01, l23);
        }
        __syncthreads();

#pragma unroll
        for (int ks = 0; ks < 2; ++ks) {
            unsigned ah[2][4], al[2][4];
#pragma unroll
            for (int mi = 0; mi < 2; ++mi) {
                const unsigned off =
                    (unsigned)((wm0 + mi * 16 + a_rsub) * 80 + (ks * 16 + a_ko) * 2);
                ldsm_x4(ah[mi][0], ah[mi][1], ah[mi][2], ah[mi][3], sbase + GAH + off);
                ldsm_x4(al[mi][0], al[mi][1], al[mi][2], al[mi][3], sbase + GAL + off);
            }
#pragma unroll
            for (int njp = 0; njp < 4; ++njp) {
                const unsigned boff =
                    (unsigned)((wn0 + njp * 16 + b_rs) * 80 + (ks * 16 + b_ko) * 2);
                unsigned bh[4], bl[4];
                ldsm_x4(bh[0], bh[1], bh[2], bh[3], sbase + GBH + boff);
                ldsm_x4(bl[0], bl[1], bl[2], bl[3], sbase + GBL + boff);
#pragma unroll
                for (int mi = 0; mi < 2; ++mi) {
                    mma_bf16(acc[mi][2 * njp],     ah[mi], bh + 0);
                    mma_bf16(acc[mi][2 * njp],     ah[mi], bl + 0);
                    mma_bf16(acc[mi][2 * njp],     al[mi], bh + 0);
                    mma_bf16(acc[mi][2 * njp + 1], ah[mi], bh + 2);
                    mma_bf16(acc[mi][2 * njp + 1], ah[mi], bl + 2);
                    mma_bf16(acc[mi][2 * njp + 1], al[mi], bh + 2);
                }
            }
        }
        __syncthreads();
    }

    // Epilogue: c0:(g,2t) c1:(g,2t+1) c2:(g+8,2t) c3:(g+8,2t+1).
#pragma unroll
    for (int mi = 0; mi < 2; ++mi) {
#pragma unroll
        for (int nj = 0; nj < 8; ++nj) {
#pragma unroll
            for (int r = 0; r < 4; ++r) {
                const int m = m0 + wm0 + mi * 16 + g + (r >= 2 ? 8 : 0);
                const int n = n0 + wn0 + nj * 8 + 2 * t + (r & 1);
                float v = acc[mi][nj][r] + bias[n];
                if (MODE == 0) {
                    const int which = n >> 10;
                    const int rem   = n & 1023;
                    const int h     = rem >> 6;
                    const int dh    = rem & 63;
                    const int b_    = m >> 11;
                    const int tkn   = m & 2047;
                    float* dst = (which == 0) ? g_Q : (which == 1) ? g_K : g_V;
                    dst[(((size_t)(b_ * HEADS + h) * SEQ) + tkn) * HDIM + dh] = v;
                } else {
                    out[(size_t)m * N + n] = v;
                }
            }
        }
    }
}

// ---------------------------------------------------------------------------
// Flash attention (R10 proven): S and PV both on bf16 m16n8k16 3-term split;
// P built in registers from S fragments.
// Smem: QH/QL [128][72b16], KH/KL/VH/VL [64][72b16], 144B stride.
// ---------------------------------------------------------------------------
#define AQH 0
#define AQL 18432
#define AKH 36864
#define AKL 46080
#define AVH 55296
#define AVL 64512
#define SM_BYTES 73728

__global__ __launch_bounds__(256, 2)
void flash_attn_mma()
{
    extern __shared__ char smc[];
    const unsigned sbase = smem_u32(smc);

    const int bh = blockIdx.y;
    const int q0 = blockIdx.x * 128;
    const float* Qp = g_Q + (size_t)bh * SEQ * HDIM;
    const float* Kp = g_K + (size_t)bh * SEQ * HDIM;
    const float* Vp = g_V + (size_t)bh * SEQ * HDIM;

    const int tid  = threadIdx.x;
    const int wid  = tid >> 5;
    const int lane = tid & 31;
    const int g    = lane >> 2;
    const int t    = lane & 3;
    const int arow = wid * 16;

    // Prologue: Q -> bf16 hi/lo tiles, pre-scaled.
#pragma unroll
    for (int it = 0; it < 8; ++it) {
        const int idx = tid + 256 * it;
        const int r = idx >> 4;
        const int c = (idx & 15) * 4;
        float4 q = *(const float4*)&Qp[(size_t)(q0 + r) * HDIM + c];
        unsigned h01, l01, h23, l23;
        bfsplit2(q.x * SCALE, q.y * SCALE, h01, l01);
        bfsplit2(q.z * SCALE, q.w * SCALE, h23, l23);
        const int bo = r * 144 + c * 2;
        *(uint2*)(smc + AQH + bo) = make_uint2(h01, h23);
        *(uint2*)(smc + AQL + bo) = make_uint2(l01, l23);
    }

    float o[8][4];
    float mrow[2] = {-1e30f, -1e30f};
    float lrow[2] = {0.f, 0.f};
#pragma unroll
    for (int nj = 0; nj < 8; ++nj)
#pragma unroll
        for (int r = 0; r < 4; ++r) o[nj][r] = 0.f;

    const unsigned FULL = 0xffffffffu;

    const int q_row = arow + (lane & 15);
    const int q_ko  = (lane >> 4) << 3;
    const int b_rs  = ((lane >> 4) << 3) + (lane & 7);
    const int b_ko  = ((lane >> 3) & 1) << 3;
    const int v_row = (((lane >> 3) & 1) << 3) + (lane & 7);
    const int v_co  = (lane >> 4) << 3;

    for (int kt = 0; kt < SEQ / 64; ++kt) {
        __syncthreads();
        // Stage K, V -> bf16 hi/lo.
#pragma unroll
        for (int it = 0; it < 4; ++it) {
            const int idx = tid + 256 * it;
            const int r = idx >> 4;
            const int c = (idx & 15) * 4;
            const int bo = r * 144 + c * 2;
            float4 kk = *(const float4*)&Kp[(size_t)(kt * 64 + r) * HDIM + c];
            unsigned h01, l01, h23, l23;
            bfsplit2(kk.x, kk.y, h01, l01);
            bfsplit2(kk.z, kk.w, h23, l23);
            *(uint2*)(smc + AKH + bo) = make_uint2(h01, h23);
            *(uint2*)(smc + AKL + bo) = make_uint2(l01, l23);
            float4 vv = *(const float4*)&Vp[(size_t)(kt * 64 + r) * HDIM + c];
            bfsplit2(vv.x, vv.y, h01, l01);
            bfsplit2(vv.z, vv.w, h23, l23);
            *(uint2*)(smc + AVH + bo) = make_uint2(h01, h23);
            *(uint2*)(smc + AVL + bo) = make_uint2(l01, l23);
        }
        __syncthreads();

        // S = (Qh+Ql) @ (Kh+Kl)^T : QhKh + QhKl + QlKh.
        float s[8][4];
#pragma unroll
        for (int nj = 0; nj < 8; ++nj)
#pragma unroll
            for (int r = 0; r < 4; ++r) s[nj][r] = 0.f;

#pragma unroll
        for (int c16 = 0; c16 < 4; ++c16) {
            const unsigned qoff = (unsigned)(q_row * 144 + (c16 * 16 + q_ko) * 2);
            unsigned ah[4], al[4];
            ldsm_x4(ah[0], ah[1], ah[2], ah[3], sbase + AQH + qoff);
            ldsm_x4(al[0], al[1], al[2], al[3], sbase + AQL + qoff);
#pragma unroll
            for (int njp = 0; njp < 4; ++njp) {
                const unsigned boff = (unsigned)((njp * 16 + b_rs) * 144
                                                 + (c16 * 16 + b_ko) * 2);
                unsigned bhv[4], blv[4];
                ldsm_x4(bhv[0], bhv[1], bhv[2], bhv[3], sbase + AKH + boff);
                ldsm_x4(blv[0], blv[1], blv[2], blv[3], sbase + AKL + boff);
                mma_bf16(s[2 * njp],     ah, bhv + 0);
                mma_bf16(s[2 * njp],     ah, blv + 0);
                mma_bf16(s[2 * njp],     al, bhv + 0);
                mma_bf16(s[2 * njp + 1], ah, bhv + 2);
                mma_bf16(s[2 * njp + 1], ah, blv + 2);
                mma_bf16(s[2 * njp + 1], al, bhv + 2);
            }
        }

        // Online softmax (rows g and g+8).
#pragma unroll
        for (int h = 0; h < 2; ++h) {
            const int r0 = 2 * h;
            float mx = -1e30f;
#pragma unroll
            for (int nj = 0; nj < 8; ++nj)
                mx = fmaxf(mx, fmaxf(s[nj][r0], s[nj][r0 + 1]));
            mx = fmaxf(mx, __shfl_xor_sync(FULL, mx, 1));
            mx = fmaxf(mx, __shfl_xor_sync(FULL, mx, 2));
            const float mnew = fmaxf(mrow[h], mx);
            const float alpha = __expf(mrow[h] - mnew);
            float rs = 0.f;
#pragma unroll
            for (int nj = 0; nj < 8; ++nj) {
                s[nj][r0]     = __expf(s[nj][r0]     - mnew);
                s[nj][r0 + 1] = __expf(s[nj][r0 + 1] - mnew);
                rs += s[nj][r0] + s[nj][r0 + 1];
            }
            rs += __shfl_xor_sync(FULL, rs, 1);
            rs += __shfl_xor_sync(FULL, rs, 2);
            lrow[h] = alpha * lrow[h] + rs;
            mrow[h] = mnew;
#pragma unroll
            for (int nj = 0; nj < 8; ++nj) {
                o[nj][r0]     *= alpha;
                o[nj][r0 + 1] *= alpha;
            }
        }

        // O += P @ V with P fragments built from S fragments (registers).
#pragma unroll
        for (int c16 = 0; c16 < 4; ++c16) {
            unsigned aph[4], apl[4];
            bfsplit2(s[2 * c16][0],     s[2 * c16][1],     aph[0], apl[0]);
            bfsplit2(s[2 * c16][2],     s[2 * c16][3],     aph[1], apl[1]);
            bfsplit2(s[2 * c16 + 1][0], s[2 * c16 + 1][1], aph[2], apl[2]);
            bfsplit2(s[2 * c16 + 1][2], s[2 * c16 + 1][3], aph[3], apl[3]);
            const unsigned vro = (unsigned)((c16 * 16 + v_row) * 144 + v_co * 2);
#pragma unroll
            for (int njp = 0; njp < 4; ++njp) {
                const unsigned voff = vro + (unsigned)(njp * 32);
                unsigned vh[4], vl[4];
                ldsm_x4t(vh[0], vh[1], vh[2], vh[3], sbase + AVH + voff);
                ldsm_x4t(vl[0], vl[1], vl[2], vl[3], sbase + AVL + voff);
                mma_bf16(o[2 * njp],     aph, vh + 0);
                mma_bf16(o[2 * njp],     aph, vl + 0);
                mma_bf16(o[2 * njp],     apl, vh + 0);
                mma_bf16(o[2 * njp + 1], aph, vh + 2);
                mma_bf16(o[2 * njp + 1], aph, vl + 2);
                mma_bf16(o[2 * njp + 1], apl, vh + 2);
            }
        }
    }

    // Epilogue: normalize, write to g_O [B,N,EMBED].
    const int h  = bh & (HEADS - 1);
    const int b  = bh >> 4;
    const float inv0 = 1.0f / lrow[0];
    const float inv1 = 1.0f / lrow[1];
    const int r0 = q0 + arow + g;
#pragma unroll
    for (int nj = 0; nj < 8; ++nj) {
        const int col = h * HDIM + nj * 8 + 2 * t;
        float2 v0 = make_float2(o[nj][0] * inv0, o[nj][1] * inv0);
        *(float2*)&g_O[(size_t)(b * SEQ + r0) * EMBED + col] = v0;
        float2 v1 = make_float2(o[nj][2] * inv1, o[nj][3] * inv1);
        *(float2*)&g_O[(size_t)(b * SEQ + r0 + 8) * EMBED + col] = v1;
    }
}

// ---------------------------------------------------------------------------
extern "C" void kernel_launch(void* const* d_in, const int* in_sizes, int n_in,
                              void* d_out, int out_size)
{
    const float* x      = (const float*)d_in[0];
    const float* w_qkv  = (const float*)d_in[1];
    const float* b_qkv  = (const float*)d_in[2];
    const float* w_proj = (const float*)d_in[3];
    const float* b_proj = (const float*)d_in[4];
    float* out = (float*)d_out;

    float* gO = nullptr;
    cudaGetSymbolAddress((void**)&gO, g_O);

    static bool attr_set = false;
    if (!attr_set) {
        cudaFuncSetAttribute(flash_attn_mma,
                             cudaFuncAttributeMaxDynamicSharedMemorySize, SM_BYTES);
        attr_set = true;
    }

    // 1) QKV projection (bf16 3-term mma) -> g_Q/g_K/g_V
    {
        dim3 grid(QKVN / 128, MTOK / 128);
        gemm_bf<0><<<grid, 256>>>(x, w_qkv, b_qkv, nullptr, MTOK, QKVN, EMBED);
    }
    // 2) Flash attention -> g_O
    {
        dim3 grid(SEQ / 128, BATCH * HEADS);
        flash_attn_mma<<<grid, 256, SM_BYTES>>>();
    }
    // 3) Output projection (bf16 3-term mma)
    {
        dim3 grid(EMBED / 128, MTOK / 128);
        gemm_bf<1><<<grid, 256>>>(gO, w_proj, b_proj, out, MTOK, EMBED, EMBED);
    }
}

// round 12
// speedup vs baseline: 1.4859x; 1.4859x over previous
#include <cuda_runtime.h>

// ---------------------------------------------------------------------------
// Fused MHA block (mma.sync only — tcgen05 unavailable at .target sm_100):
//   QKV GEMM  : fp16 m16n8k16 single-term + ldmatrix  [NEW: 2x K/inst vs tf32]
//   attention : S bf16 3-term + register-P PV bf16 3-term (R10/R11 proven)
//   proj GEMM : fp16 m16n8k16 single-term + ldmatrix  [NEW]
// Shapes: B=2, N=2048, EMBED=1024, HEADS=16, HDIM=64.
// ---------------------------------------------------------------------------

#define BATCH  2
#define SEQ    2048
#define EMBED  1024
#define HEADS  16
#define HDIM   64
#define MTOK   (BATCH * SEQ)      // 4096
#define QKVN   (3 * EMBED)        // 3072
#define SCALE  0.125f             // HDIM^-0.5

__device__ float g_Q[BATCH * HEADS * SEQ * HDIM];   // [B,H,N,Dh]
__device__ float g_K[BATCH * HEADS * SEQ * HDIM];
__device__ float g_V[BATCH * HEADS * SEQ * HDIM];
__device__ float g_O[BATCH * SEQ * EMBED];          // attention output [B,N,EMBED]

// ------------------------------- helpers -----------------------------------
// Pack two floats into f16x2 / bf16x2: f0 -> low half, f1 -> high half.
__device__ __forceinline__ unsigned pk_f16(float f0, float f1) {
    unsigned d;
    asm("cvt.rn.f16x2.f32 %0, %1, %2;" : "=r"(d) : "f"(f1), "f"(f0));
    return d;
}
__device__ __forceinline__ unsigned pk_bf(float f0, float f1) {
    unsigned d;
    asm("cvt.rn.bf16x2.f32 %0, %1, %2;" : "=r"(d) : "f"(f1), "f"(f0));
    return d;
}
// Split a float pair into bf16 hi-pair + residual lo-pair.
__device__ __forceinline__ void bfsplit2(float f0, float f1, unsigned& hi, unsigned& lo) {
    hi = pk_bf(f0, f1);
    float e0 = __uint_as_float(hi << 16);
    float e1 = __uint_as_float(hi & 0xffff0000u);
    lo = pk_bf(f0 - e0, f1 - e1);
}
__device__ __forceinline__ void mma_bf16(float* c, const unsigned* a, const unsigned* b) {
    asm volatile(
        "mma.sync.aligned.m16n8k16.row.col.f32.bf16.bf16.f32 "
        "{%0,%1,%2,%3}, {%4,%5,%6,%7}, {%8,%9}, {%0,%1,%2,%3};\n"
        : "+f"(c[0]), "+f"(c[1]), "+f"(c[2]), "+f"(c[3])
        : "r"(a[0]), "r"(a[1]), "r"(a[2]), "r"(a[3]),
          "r"(b[0]), "r"(b[1]));
}
__device__ __forceinline__ void mma_f16(float* c, const unsigned* a, const unsigned* b) {
    asm volatile(
        "mma.sync.aligned.m16n8k16.row.col.f32.f16.f16.f32 "
        "{%0,%1,%2,%3}, {%4,%5,%6,%7}, {%8,%9}, {%0,%1,%2,%3};\n"
        : "+f"(c[0]), "+f"(c[1]), "+f"(c[2]), "+f"(c[3])
        : "r"(a[0]), "r"(a[1]), "r"(a[2]), "r"(a[3]),
          "r"(b[0]), "r"(b[1]));
}
__device__ __forceinline__ void ldsm_x4(unsigned& r0, unsigned& r1,
                                        unsigned& r2, unsigned& r3, unsigned addr) {
    asm volatile("ldmatrix.sync.aligned.m8n8.x4.shared.b16 {%0,%1,%2,%3}, [%4];"
                 : "=r"(r0), "=r"(r1), "=r"(r2), "=r"(r3) : "r"(addr));
}
__device__ __forceinline__ void ldsm_x4t(unsigned& r0, unsigned& r1,
                                         unsigned& r2, unsigned& r3, unsigned addr) {
    asm volatile("ldmatrix.sync.aligned.m8n8.x4.trans.shared.b16 {%0,%1,%2,%3}, [%4];"
                 : "=r"(r0), "=r"(r1), "=r"(r2), "=r"(r3) : "r"(addr));
}
__device__ __forceinline__ unsigned smem_u32(const void* p) {
    return (unsigned)__cvta_generic_to_shared(p);
}

// ---------------------------------------------------------------------------
// GEMM: C[M,N] = A[M,K] @ W[N,K]^T + bias[N]
// fp16 m16n8k16 single-term (fp16 mantissa == tf32 mantissa; 2x K per inst).
// 128x128 tile, BK=32, 256 threads = 8 warps (4M x 2N), warp tile 32x64.
// Smem: AH/BH, 128 rows x 80B stride (64B data + 16B pad). Conflict-free ldsm
// (r*20 mod 32 spans distinct bank quads).
// ---------------------------------------------------------------------------
#define GA 0
#define GB 10240

template <int MODE>
__global__ __launch_bounds__(256, 2)
void gemm_fp16(const float* __restrict__ A, const float* __restrict__ W,
               const float* __restrict__ bias, float* __restrict__ out,
               int M, int N, int K)
{
    __shared__ char smc[2 * 128 * 80];
    const unsigned sbase = smem_u32(smc);

    const int tid  = threadIdx.x;
    const int wid  = tid >> 5;
    const int lane = tid & 31;
    const int g    = lane >> 2;
    const int t    = lane & 3;

    const int wm0 = (wid & 3) * 32;
    const int wn0 = (wid >> 2) * 64;

    const int m0 = blockIdx.y * 128;
    const int n0 = blockIdx.x * 128;

    float acc[2][8][4];
#pragma unroll
    for (int mi = 0; mi < 2; ++mi)
#pragma unroll
        for (int nj = 0; nj < 8; ++nj)
#pragma unroll
            for (int r = 0; r < 4; ++r) acc[mi][nj][r] = 0.f;

    const int a_rsub = lane & 15;
    const int a_ko   = (lane >> 4) << 3;
    const int b_rs   = ((lane >> 4) << 3) + (lane & 7);
    const int b_ko   = ((lane >> 3) & 1) << 3;

    for (int k0 = 0; k0 < K; k0 += 32) {
        // Stage: A tile 128x32 + B tile 128x32 -> fp16 (8 f4/thread).
#pragma unroll
        for (int i = 0; i < 8; ++i) {
            const int idx = tid + 256 * i;         // 0..2047
            const int f   = idx & 1023;
            const int row = f >> 3;                // 0..127
            const int c4  = (f & 7) * 4;           // 0..28
            const float* src = (idx < 1024) ? &A[(size_t)(m0 + row) * K + k0 + c4]
                                            : &W[(size_t)(n0 + row) * K + k0 + c4];
            float4 v = *(const float4*)src;
            const int dst = ((idx < 1024) ? GA : GB) + row * 80 + c4 * 2;
            *(uint2*)(smc + dst) = make_uint2(pk_f16(v.x, v.y), pk_f16(v.z, v.w));
        }
        __syncthreads();

#pragma unroll
        for (int ks = 0; ks < 2; ++ks) {
            unsigned a[2][4];
#pragma unroll
            for (int mi = 0; mi < 2; ++mi) {
                const unsigned off =
                    (unsigned)((wm0 + mi * 16 + a_rsub) * 80 + (ks * 16 + a_ko) * 2);
                ldsm_x4(a[mi][0], a[mi][1], a[mi][2], a[mi][3], sbase + GA + off);
            }
#pragma unroll
            for (int njp = 0; njp < 4; ++njp) {
                const unsigned boff =
                    (unsigned)((wn0 + njp * 16 + b_rs) * 80 + (ks * 16 + b_ko) * 2);
                unsigned b[4];
                ldsm_x4(b[0], b[1], b[2], b[3], sbase + GB + boff);
#pragma unroll
                for (int mi = 0; mi < 2; ++mi) {
                    mma_f16(acc[mi][2 * njp],     a[mi], b + 0);
                    mma_f16(acc[mi][2 * njp + 1], a[mi], b + 2);
                }
            }
        }
        __syncthreads();
    }

    // Epilogue: c0:(g,2t) c1:(g,2t+1) c2:(g+8,2t) c3:(g+8,2t+1).
#pragma unroll
    for (int mi = 0; mi < 2; ++mi) {
#pragma unroll
        for (int nj = 0; nj < 8; ++nj) {
#pragma unroll
            for (int r = 0; r < 4; ++r) {
                const int m = m0 + wm0 + mi * 16 + g + (r >= 2 ? 8 : 0);
                const int n = n0 + wn0 + nj * 8 + 2 * t + (r & 1);
                float v = acc[mi][nj][r] + bias[n];
                if (MODE == 0) {
                    const int which = n >> 10;
                    const int rem   = n & 1023;
                    const int h     = rem >> 6;
                    const int dh    = rem & 63;
                    const int b_    = m >> 11;
                    const int tkn   = m & 2047;
                    float* dst = (which == 0) ? g_Q : (which == 1) ? g_K : g_V;
                    dst[(((size_t)(b_ * HEADS + h) * SEQ) + tkn) * HDIM + dh] = v;
                } else {
                    out[(size_t)m * N + n] = v;
                }
            }
        }
    }
}

// ---------------------------------------------------------------------------
// Flash attention (R10/R11 proven): S and PV both on bf16 m16n8k16 3-term;
// P built in registers from S fragments.
// Smem: QH/QL [128][72b16], KH/KL/VH/VL [64][72b16], 144B stride.
// ---------------------------------------------------------------------------
#define AQH 0
#define AQL 18432
#define AKH 36864
#define AKL 46080
#define AVH 55296
#define AVL 64512
#define SM_BYTES 73728

__global__ __launch_bounds__(256, 2)
void flash_attn_mma()
{
    extern __shared__ char smc[];
    const unsigned sbase = smem_u32(smc);

    const int bh = blockIdx.y;
    const int q0 = blockIdx.x * 128;
    const float* Qp = g_Q + (size_t)bh * SEQ * HDIM;
    const float* Kp = g_K + (size_t)bh * SEQ * HDIM;
    const float* Vp = g_V + (size_t)bh * SEQ * HDIM;

    const int tid  = threadIdx.x;
    const int wid  = tid >> 5;
    const int lane = tid & 31;
    const int g    = lane >> 2;
    const int t    = lane & 3;
    const int arow = wid * 16;

    // Prologue: Q -> bf16 hi/lo tiles, pre-scaled.
#pragma unroll
    for (int it = 0; it < 8; ++it) {
        const int idx = tid + 256 * it;
        const int r = idx >> 4;
        const int c = (idx & 15) * 4;
        float4 q = *(const float4*)&Qp[(size_t)(q0 + r) * HDIM + c];
        unsigned h01, l01, h23, l23;
        bfsplit2(q.x * SCALE, q.y * SCALE, h01, l01);
        bfsplit2(q.z * SCALE, q.w * SCALE, h23, l23);
        const int bo = r * 144 + c * 2;
        *(uint2*)(smc + AQH + bo) = make_uint2(h01, h23);
        *(uint2*)(smc + AQL + bo) = make_uint2(l01, l23);
    }

    float o[8][4];
    float mrow[2] = {-1e30f, -1e30f};
    float lrow[2] = {0.f, 0.f};
#pragma unroll
    for (int nj = 0; nj < 8; ++nj)
#pragma unroll
        for (int r = 0; r < 4; ++r) o[nj][r] = 0.f;

    const unsigned FULL = 0xffffffffu;

    const int q_row = arow + (lane & 15);
    const int q_ko  = (lane >> 4) << 3;
    const int b_rs  = ((lane >> 4) << 3) + (lane & 7);
    const int b_ko  = ((lane >> 3) & 1) << 3;
    const int v_row = (((lane >> 3) & 1) << 3) + (lane & 7);
    const int v_co  = (lane >> 4) << 3;

    for (int kt = 0; kt < SEQ / 64; ++kt) {
        __syncthreads();
        // Stage K, V -> bf16 hi/lo.
#pragma unroll
        for (int it = 0; it < 4; ++it) {
            const int idx = tid + 256 * it;
            const int r = idx >> 4;
            const int c = (idx & 15) * 4;
            const int bo = r * 144 + c * 2;
            float4 kk = *(const float4*)&Kp[(size_t)(kt * 64 + r) * HDIM + c];
            unsigned h01, l01, h23, l23;
            bfsplit2(kk.x, kk.y, h01, l01);
            bfsplit2(kk.z, kk.w, h23, l23);
            *(uint2*)(smc + AKH + bo) = make_uint2(h01, h23);
            *(uint2*)(smc + AKL + bo) = make_uint2(l01, l23);
            float4 vv = *(const float4*)&Vp[(size_t)(kt * 64 + r) * HDIM + c];
            bfsplit2(vv.x, vv.y, h01, l01);
            bfsplit2(vv.z, vv.w, h23, l23);
            *(uint2*)(smc + AVH + bo) = make_uint2(h01, h23);
            *(uint2*)(smc + AVL + bo) = make_uint2(l01, l23);
        }
        __syncthreads();

        // S = (Qh+Ql) @ (Kh+Kl)^T : QhKh + QhKl + QlKh.
        float s[8][4];
#pragma unroll
        for (int nj = 0; nj < 8; ++nj)
#pragma unroll
            for (int r = 0; r < 4; ++r) s[nj][r] = 0.f;

#pragma unroll
        for (int c16 = 0; c16 < 4; ++c16) {
            const unsigned qoff = (unsigned)(q_row * 144 + (c16 * 16 + q_ko) * 2);
            unsigned ah[4], al[4];
            ldsm_x4(ah[0], ah[1], ah[2], ah[3], sbase + AQH + qoff);
            ldsm_x4(al[0], al[1], al[2], al[3], sbase + AQL + qoff);
#pragma unroll
            for (int njp = 0; njp < 4; ++njp) {
                const unsigned boff = (unsigned)((njp * 16 + b_rs) * 144
                                                 + (c16 * 16 + b_ko) * 2);
                unsigned bhv[4], blv[4];
                ldsm_x4(bhv[0], bhv[1], bhv[2], bhv[3], sbase + AKH + boff);
                ldsm_x4(blv[0], blv[1], blv[2], blv[3], sbase + AKL + boff);
                mma_bf16(s[2 * njp],     ah, bhv + 0);
                mma_bf16(s[2 * njp],     ah, blv + 0);
                mma_bf16(s[2 * njp],     al, bhv + 0);
                mma_bf16(s[2 * njp + 1], ah, bhv + 2);
                mma_bf16(s[2 * njp + 1], ah, blv + 2);
                mma_bf16(s[2 * njp + 1], al, bhv + 2);
            }
        }

        // Online softmax (rows g and g+8).
#pragma unroll
        for (int h = 0; h < 2; ++h) {
            const int r0 = 2 * h;
            float mx = -1e30f;
#pragma unroll
            for (int nj = 0; nj < 8; ++nj)
                mx = fmaxf(mx, fmaxf(s[nj][r0], s[nj][r0 + 1]));
            mx = fmaxf(mx, __shfl_xor_sync(FULL, mx, 1));
            mx = fmaxf(mx, __shfl_xor_sync(FULL, mx, 2));
            const float mnew = fmaxf(mrow[h], mx);
            const float alpha = __expf(mrow[h] - mnew);
            float rs = 0.f;
#pragma unroll
            for (int nj = 0; nj < 8; ++nj) {
                s[nj][r0]     = __expf(s[nj][r0]     - mnew);
                s[nj][r0 + 1] = __expf(s[nj][r0 + 1] - mnew);
                rs += s[nj][r0] + s[nj][r0 + 1];
            }
            rs += __shfl_xor_sync(FULL, rs, 1);
            rs += __shfl_xor_sync(FULL, rs, 2);
            lrow[h] = alpha * lrow[h] + rs;
            mrow[h] = mnew;
#pragma unroll
            for (int nj = 0; nj < 8; ++nj) {
                o[nj][r0]     *= alpha;
                o[nj][r0 + 1] *= alpha;
            }
        }

        // O += P @ V with P fragments built from S fragments (registers).
#pragma unroll
        for (int c16 = 0; c16 < 4; ++c16) {
            unsigned aph[4], apl[4];
            bfsplit2(s[2 * c16][0],     s[2 * c16][1],     aph[0], apl[0]);
            bfsplit2(s[2 * c16][2],     s[2 * c16][3],     aph[1], apl[1]);
            bfsplit2(s[2 * c16 + 1][0], s[2 * c16 + 1][1], aph[2], apl[2]);
            bfsplit2(s[2 * c16 + 1][2], s[2 * c16 + 1][3], aph[3], apl[3]);
            const unsigned vro = (unsigned)((c16 * 16 + v_row) * 144 + v_co * 2);
#pragma unroll
            for (int njp = 0; njp < 4; ++njp) {
                const unsigned voff = vro + (unsigned)(njp * 32);
                unsigned vh[4], vl[4];
                ldsm_x4t(vh[0], vh[1], vh[2], vh[3], sbase + AVH + voff);
                ldsm_x4t(vl[0], vl[1], vl[2], vl[3], sbase + AVL + voff);
                mma_bf16(o[2 * njp],     aph, vh + 0);
                mma_bf16(o[2 * njp],     aph, vl + 0);
                mma_bf16(o[2 * njp],     apl, vh + 0);
                mma_bf16(o[2 * njp + 1], aph, vh + 2);
                mma_bf16(o[2 * njp + 1], aph, vl + 2);
                mma_bf16(o[2 * njp + 1], apl, vh + 2);
            }
        }
    }

    // Epilogue: normalize, write to g_O [B,N,EMBED].
    const int h  = bh & (HEADS - 1);
    const int b  = bh >> 4;
    const float inv0 = 1.0f / lrow[0];
    const float inv1 = 1.0f / lrow[1];
    const int r0 = q0 + arow + g;
#pragma unroll
    for (int nj = 0; nj < 8; ++nj) {
        const int col = h * HDIM + nj * 8 + 2 * t;
        float2 v0 = make_float2(o[nj][0] * inv0, o[nj][1] * inv0);
        *(float2*)&g_O[(size_t)(b * SEQ + r0) * EMBED + col] = v0;
        float2 v1 = make_float2(o[nj][2] * inv1, o[nj][3] * inv1);
        *(float2*)&g_O[(size_t)(b * SEQ + r0 + 8) * EMBED + col] = v1;
    }
}

// ---------------------------------------------------------------------------
extern "C" void kernel_launch(void* const* d_in, const int* in_sizes, int n_in,
                              void* d_out, int out_size)
{
    const float* x      = (const float*)d_in[0];
    const float* w_qkv  = (const float*)d_in[1];
    const float* b_qkv  = (const float*)d_in[2];
    const float* w_proj = (const float*)d_in[3];
    const float* b_proj = (const float*)d_in[4];
    float* out = (float*)d_out;

    float* gO = nullptr;
    cudaGetSymbolAddress((void**)&gO, g_O);

    static bool attr_set = false;
    if (!attr_set) {
        cudaFuncSetAttribute(flash_attn_mma,
                             cudaFuncAttributeMaxDynamicSharedMemorySize, SM_BYTES);
        attr_set = true;
    }

    // 1) QKV projection (fp16 mma) -> g_Q/g_K/g_V
    {
        dim3 grid(QKVN / 128, MTOK / 128);
        gemm_fp16<0><<<grid, 256>>>(x, w_qkv, b_qkv, nullptr, MTOK, QKVN, EMBED);
    }
    // 2) Flash attention -> g_O
    {
        dim3 grid(SEQ / 128, BATCH * HEADS);
        flash_attn_mma<<<grid, 256, SM_BYTES>>>();
    }
    // 3) Output projection (fp16 mma)
    {
        dim3 grid(EMBED / 128, MTOK / 128);
        gemm_fp16<1><<<grid, 256>>>(gO, w_proj, b_proj, out, MTOK, EMBED, EMBED);
    }
}

// round 13
// speedup vs baseline: 2.0638x; 1.3889x over previous
#include <cuda_runtime.h>

// ---------------------------------------------------------------------------
// Fused MHA block (mma.sync only — tcgen05 unavailable at .target sm_100):
//   QKV GEMM  : fp16 m16n8k16 single-term + ldmatrix (R12 proven, 173us)
//   attention : S and PV fp16 m16n8k16 single-term [NEW: 3x fewer mma]
//   proj GEMM : fp16 m16n8k16 single-term (R12 proven)
// Error budget (measured): GEMMs 5.5e-4, PV-single ~3.1e-4, S-single(K=64)
// ~1.5e-4 -> total ~6.6e-4 < 1e-3.
// Shapes: B=2, N=2048, EMBED=1024, HEADS=16, HDIM=64.
// ---------------------------------------------------------------------------

#define BATCH  2
#define SEQ    2048
#define EMBED  1024
#define HEADS  16
#define HDIM   64
#define MTOK   (BATCH * SEQ)      // 4096
#define QKVN   (3 * EMBED)        // 3072
#define SCALE  0.125f             // HDIM^-0.5

__device__ float g_Q[BATCH * HEADS * SEQ * HDIM];   // [B,H,N,Dh]
__device__ float g_K[BATCH * HEADS * SEQ * HDIM];
__device__ float g_V[BATCH * HEADS * SEQ * HDIM];
__device__ float g_O[BATCH * SEQ * EMBED];          // attention output [B,N,EMBED]

// ------------------------------- helpers -----------------------------------
__device__ __forceinline__ unsigned pk_f16(float f0, float f1) {
    unsigned d;
    asm("cvt.rn.f16x2.f32 %0, %1, %2;" : "=r"(d) : "f"(f1), "f"(f0));
    return d;
}
__device__ __forceinline__ void mma_f16(float* c, const unsigned* a, const unsigned* b) {
    asm volatile(
        "mma.sync.aligned.m16n8k16.row.col.f32.f16.f16.f32 "
        "{%0,%1,%2,%3}, {%4,%5,%6,%7}, {%8,%9}, {%0,%1,%2,%3};\n"
        : "+f"(c[0]), "+f"(c[1]), "+f"(c[2]), "+f"(c[3])
        : "r"(a[0]), "r"(a[1]), "r"(a[2]), "r"(a[3]),
          "r"(b[0]), "r"(b[1]));
}
__device__ __forceinline__ void ldsm_x4(unsigned& r0, unsigned& r1,
                                        unsigned& r2, unsigned& r3, unsigned addr) {
    asm volatile("ldmatrix.sync.aligned.m8n8.x4.shared.b16 {%0,%1,%2,%3}, [%4];"
                 : "=r"(r0), "=r"(r1), "=r"(r2), "=r"(r3) : "r"(addr));
}
__device__ __forceinline__ void ldsm_x4t(unsigned& r0, unsigned& r1,
                                         unsigned& r2, unsigned& r3, unsigned addr) {
    asm volatile("ldmatrix.sync.aligned.m8n8.x4.trans.shared.b16 {%0,%1,%2,%3}, [%4];"
                 : "=r"(r0), "=r"(r1), "=r"(r2), "=r"(r3) : "r"(addr));
}
__device__ __forceinline__ unsigned smem_u32(const void* p) {
    return (unsigned)__cvta_generic_to_shared(p);
}

// ---------------------------------------------------------------------------
// GEMM: C[M,N] = A[M,K] @ W[N,K]^T + bias[N]   (fp16 m16n8k16, R12 proven)
// ---------------------------------------------------------------------------
#define GA 0
#define GB 10240

template <int MODE>
__global__ __launch_bounds__(256, 2)
void gemm_fp16(const float* __restrict__ A, const float* __restrict__ W,
               const float* __restrict__ bias, float* __restrict__ out,
               int M, int N, int K)
{
    __shared__ char smc[2 * 128 * 80];
    const unsigned sbase = smem_u32(smc);

    const int tid  = threadIdx.x;
    const int wid  = tid >> 5;
    const int lane = tid & 31;
    const int g    = lane >> 2;
    const int t    = lane & 3;

    const int wm0 = (wid & 3) * 32;
    const int wn0 = (wid >> 2) * 64;

    const int m0 = blockIdx.y * 128;
    const int n0 = blockIdx.x * 128;

    float acc[2][8][4];
#pragma unroll
    for (int mi = 0; mi < 2; ++mi)
#pragma unroll
        for (int nj = 0; nj < 8; ++nj)
#pragma unroll
            for (int r = 0; r < 4; ++r) acc[mi][nj][r] = 0.f;

    const int a_rsub = lane & 15;
    const int a_ko   = (lane >> 4) << 3;
    const int b_rs   = ((lane >> 4) << 3) + (lane & 7);
    const int b_ko   = ((lane >> 3) & 1) << 3;

    for (int k0 = 0; k0 < K; k0 += 32) {
#pragma unroll
        for (int i = 0; i < 8; ++i) {
            const int idx = tid + 256 * i;
            const int f   = idx & 1023;
            const int row = f >> 3;
            const int c4  = (f & 7) * 4;
            const float* src = (idx < 1024) ? &A[(size_t)(m0 + row) * K + k0 + c4]
                                            : &W[(size_t)(n0 + row) * K + k0 + c4];
            float4 v = *(const float4*)src;
            const int dst = ((idx < 1024) ? GA : GB) + row * 80 + c4 * 2;
            *(uint2*)(smc + dst) = make_uint2(pk_f16(v.x, v.y), pk_f16(v.z, v.w));
        }
        __syncthreads();

#pragma unroll
        for (int ks = 0; ks < 2; ++ks) {
            unsigned a[2][4];
#pragma unroll
            for (int mi = 0; mi < 2; ++mi) {
                const unsigned off =
                    (unsigned)((wm0 + mi * 16 + a_rsub) * 80 + (ks * 16 + a_ko) * 2);
                ldsm_x4(a[mi][0], a[mi][1], a[mi][2], a[mi][3], sbase + GA + off);
            }
#pragma unroll
            for (int njp = 0; njp < 4; ++njp) {
                const unsigned boff =
                    (unsigned)((wn0 + njp * 16 + b_rs) * 80 + (ks * 16 + b_ko) * 2);
                unsigned b[4];
                ldsm_x4(b[0], b[1], b[2], b[3], sbase + GB + boff);
#pragma unroll
                for (int mi = 0; mi < 2; ++mi) {
                    mma_f16(acc[mi][2 * njp],     a[mi], b + 0);
                    mma_f16(acc[mi][2 * njp + 1], a[mi], b + 2);
                }
            }
        }
        __syncthreads();
    }

#pragma unroll
    for (int mi = 0; mi < 2; ++mi) {
#pragma unroll
        for (int nj = 0; nj < 8; ++nj) {
#pragma unroll
            for (int r = 0; r < 4; ++r) {
                const int m = m0 + wm0 + mi * 16 + g + (r >= 2 ? 8 : 0);
                const int n = n0 + wn0 + nj * 8 + 2 * t + (r & 1);
                float v = acc[mi][nj][r] + bias[n];
                if (MODE == 0) {
                    const int which = n >> 10;
                    const int rem   = n & 1023;
                    const int h     = rem >> 6;
                    const int dh    = rem & 63;
                    const int b_    = m >> 11;
                    const int tkn   = m & 2047;
                    float* dst = (which == 0) ? g_Q : (which == 1) ? g_K : g_V;
                    dst[(((size_t)(b_ * HEADS + h) * SEQ) + tkn) * HDIM + dh] = v;
                } else {
                    out[(size_t)m * N + n] = v;
                }
            }
        }
    }
}

// ---------------------------------------------------------------------------
// Flash attention: S and PV both fp16 m16n8k16 single-term.
// 1 CTA per (bh, 128 q-rows); 8 warps x (16 q-rows x 64 kv). KV tile 64.
// Smem: QF [128][72f16] 18432 | KF [64][72] 9216 | VF 9216  = 36864 B.
// 144B stride: all ldsm phases conflict-free (r*36 mod 32 spans quads).
// ---------------------------------------------------------------------------
#define AQF 0
#define AKF 18432
#define AVF 27648
#define SM_BYTES 36864

__global__ __launch_bounds__(256, 2)
void flash_attn_mma()
{
    extern __shared__ char smc[];
    const unsigned sbase = smem_u32(smc);

    const int bh = blockIdx.y;
    const int q0 = blockIdx.x * 128;
    const float* Qp = g_Q + (size_t)bh * SEQ * HDIM;
    const float* Kp = g_K + (size_t)bh * SEQ * HDIM;
    const float* Vp = g_V + (size_t)bh * SEQ * HDIM;

    const int tid  = threadIdx.x;
    const int wid  = tid >> 5;
    const int lane = tid & 31;
    const int g    = lane >> 2;
    const int t    = lane & 3;
    const int arow = wid * 16;

    // Prologue: Q -> fp16 tile, pre-scaled.
#pragma unroll
    for (int it = 0; it < 8; ++it) {
        const int idx = tid + 256 * it;      // 0..2047 over 128x16 f4
        const int r = idx >> 4;
        const int c = (idx & 15) * 4;
        float4 q = *(const float4*)&Qp[(size_t)(q0 + r) * HDIM + c];
        *(uint2*)(smc + AQF + r * 144 + c * 2) =
            make_uint2(pk_f16(q.x * SCALE, q.y * SCALE),
                       pk_f16(q.z * SCALE, q.w * SCALE));
    }

    float o[8][4];
    float mrow[2] = {-1e30f, -1e30f};
    float lrow[2] = {0.f, 0.f};
#pragma unroll
    for (int nj = 0; nj < 8; ++nj)
#pragma unroll
        for (int r = 0; r < 4; ++r) o[nj][r] = 0.f;

    const unsigned FULL = 0xffffffffu;

    const int q_row = arow + (lane & 15);
    const int q_ko  = (lane >> 4) << 3;
    const int b_rs  = ((lane >> 4) << 3) + (lane & 7);
    const int b_ko  = ((lane >> 3) & 1) << 3;
    const int v_row = (((lane >> 3) & 1) << 3) + (lane & 7);
    const int v_co  = (lane >> 4) << 3;

    for (int kt = 0; kt < SEQ / 64; ++kt) {
        __syncthreads();   // prior ldsm reads done; K/V tiles free
        // Stage K, V -> fp16 tiles (1024 f4 total; 4 f4/thread).
#pragma unroll
        for (int it = 0; it < 4; ++it) {
            const int idx = tid + 256 * it;  // 0..1023 over 64x16 f4
            const int r = idx >> 4;
            const int c = (idx & 15) * 4;
            const int bo = r * 144 + c * 2;
            float4 kk = *(const float4*)&Kp[(size_t)(kt * 64 + r) * HDIM + c];
            *(uint2*)(smc + AKF + bo) =
                make_uint2(pk_f16(kk.x, kk.y), pk_f16(kk.z, kk.w));
            float4 vv = *(const float4*)&Vp[(size_t)(kt * 64 + r) * HDIM + c];
            *(uint2*)(smc + AVF + bo) =
                make_uint2(pk_f16(vv.x, vv.y), pk_f16(vv.z, vv.w));
        }
        __syncthreads();

        // S = Q @ K^T (fp16 single-term).
        float s[8][4];
#pragma unroll
        for (int nj = 0; nj < 8; ++nj)
#pragma unroll
            for (int r = 0; r < 4; ++r) s[nj][r] = 0.f;

#pragma unroll
        for (int c16 = 0; c16 < 4; ++c16) {
            const unsigned qoff = (unsigned)(q_row * 144 + (c16 * 16 + q_ko) * 2);
            unsigned a[4];
            ldsm_x4(a[0], a[1], a[2], a[3], sbase + AQF + qoff);
#pragma unroll
            for (int njp = 0; njp < 4; ++njp) {
                const unsigned boff = (unsigned)((njp * 16 + b_rs) * 144
                                                 + (c16 * 16 + b_ko) * 2);
                unsigned b[4];
                ldsm_x4(b[0], b[1], b[2], b[3], sbase + AKF + boff);
                mma_f16(s[2 * njp],     a, b + 0);
                mma_f16(s[2 * njp + 1], a, b + 2);
            }
        }

        // Online softmax (rows g and g+8).
#pragma unroll
        for (int h = 0; h < 2; ++h) {
            const int r0 = 2 * h;
            float mx = -1e30f;
#pragma unroll
            for (int nj = 0; nj < 8; ++nj)
                mx = fmaxf(mx, fmaxf(s[nj][r0], s[nj][r0 + 1]));
            mx = fmaxf(mx, __shfl_xor_sync(FULL, mx, 1));
            mx = fmaxf(mx, __shfl_xor_sync(FULL, mx, 2));
            const float mnew = fmaxf(mrow[h], mx);
            const float alpha = __expf(mrow[h] - mnew);
            float rs = 0.f;
#pragma unroll
            for (int nj = 0; nj < 8; ++nj) {
                s[nj][r0]     = __expf(s[nj][r0]     - mnew);
                s[nj][r0 + 1] = __expf(s[nj][r0 + 1] - mnew);
                rs += s[nj][r0] + s[nj][r0 + 1];
            }
            rs += __shfl_xor_sync(FULL, rs, 1);
            rs += __shfl_xor_sync(FULL, rs, 2);
            lrow[h] = alpha * lrow[h] + rs;
            mrow[h] = mnew;
#pragma unroll
            for (int nj = 0; nj < 8; ++nj) {
                o[nj][r0]     *= alpha;
                o[nj][r0 + 1] *= alpha;
            }
        }

        // O += P @ V, P fragments built from S fragments (fp16, registers).
#pragma unroll
        for (int c16 = 0; c16 < 4; ++c16) {
            unsigned ap[4];
            ap[0] = pk_f16(s[2 * c16][0],     s[2 * c16][1]);
            ap[1] = pk_f16(s[2 * c16][2],     s[2 * c16][3]);
            ap[2] = pk_f16(s[2 * c16 + 1][0], s[2 * c16 + 1][1]);
            ap[3] = pk_f16(s[2 * c16 + 1][2], s[2 * c16 + 1][3]);
            const unsigned vro = (unsigned)((c16 * 16 + v_row) * 144 + v_co * 2);
#pragma unroll
            for (int njp = 0; njp < 4; ++njp) {
                const unsigned voff = vro + (unsigned)(njp * 32);
                unsigned vb[4];
                ldsm_x4t(vb[0], vb[1], vb[2], vb[3], sbase + AVF + voff);
                mma_f16(o[2 * njp],     ap, vb + 0);
                mma_f16(o[2 * njp + 1], ap, vb + 2);
            }
        }
    }

    // Epilogue: normalize, write to g_O [B,N,EMBED].
    const int h  = bh & (HEADS - 1);
    const int b  = bh >> 4;
    const float inv0 = 1.0f / lrow[0];
    const float inv1 = 1.0f / lrow[1];
    const int r0 = q0 + arow + g;
#pragma unroll
    for (int nj = 0; nj < 8; ++nj) {
        const int col = h * HDIM + nj * 8 + 2 * t;
        float2 v0 = make_float2(o[nj][0] * inv0, o[nj][1] * inv0);
        *(float2*)&g_O[(size_t)(b * SEQ + r0) * EMBED + col] = v0;
        float2 v1 = make_float2(o[nj][2] * inv1, o[nj][3] * inv1);
        *(float2*)&g_O[(size_t)(b * SEQ + r0 + 8) * EMBED + col] = v1;
    }
}

// ---------------------------------------------------------------------------
extern "C" void kernel_launch(void* const* d_in, const int* in_sizes, int n_in,
                              void* d_out, int out_size)
{
    const float* x      = (const float*)d_in[0];
    const float* w_qkv  = (const float*)d_in[1];
    const float* b_qkv  = (const float*)d_in[2];
    const float* w_proj = (const float*)d_in[3];
    const float* b_proj = (const float*)d_in[4];
    float* out = (float*)d_out;

    float* gO = nullptr;
    cudaGetSymbolAddress((void**)&gO, g_O);

    static bool attr_set = false;
    if (!attr_set) {
        cudaFuncSetAttribute(flash_attn_mma,
                             cudaFuncAttributeMaxDynamicSharedMemorySize, SM_BYTES);
        attr_set = true;
    }

    // 1) QKV projection (fp16 mma) -> g_Q/g_K/g_V
    {
        dim3 grid(QKVN / 128, MTOK / 128);
        gemm_fp16<0><<<grid, 256>>>(x, w_qkv, b_qkv, nullptr, MTOK, QKVN, EMBED);
    }
    // 2) Flash attention (fp16 single-term) -> g_O
    {
        dim3 grid(SEQ / 128, BATCH * HEADS);
        flash_attn_mma<<<grid, 256, SM_BYTES>>>();
    }
    // 3) Output projection (fp16 mma)
    {
        dim3 grid(EMBED / 128, MTOK / 128);
        gemm_fp16<1><<<grid, 256>>>(gO, w_proj, b_proj, out, MTOK, EMBED, EMBED);
    }
}

// round 14
// speedup vs baseline: 2.8037x; 1.3585x over previous
#include <cuda_runtime.h>
#include <cuda_fp16.h>

// ---------------------------------------------------------------------------
// Fused MHA block, all-fp16 mma.sync with cp.async pipelines:
//   prep      : x, w_qkv, w_proj -> fp16 (one rounding, same as before)
//   QKV GEMM  : fp16 m16n8k16, BK=64, 2-stage cp.async; writes fp16 Q/K/V
//   attention : fp16 S+PV (R13 proven math), cp.async KV double-buffer,
//               fp16 O output
//   proj GEMM : fp16, cp.async, fp32 output + bias
// Shapes: B=2, N=2048, EMBED=1024, HEADS=16, HDIM=64.
// ---------------------------------------------------------------------------

#define BATCH  2
#define SEQ    2048
#define EMBED  1024
#define HEADS  16
#define HDIM   64
#define MTOK   (BATCH * SEQ)      // 4096
#define QKVN   (3 * EMBED)        // 3072
#define SCALE  0.125f             // HDIM^-0.5

__device__ __half g_xh[MTOK * EMBED];
__device__ __half g_wqh[QKVN * EMBED];
__device__ __half g_wph[EMBED * EMBED];
__device__ __half g_Qh[BATCH * HEADS * SEQ * HDIM];   // pre-scaled by 0.125
__device__ __half g_Kh[BATCH * HEADS * SEQ * HDIM];
__device__ __half g_Vh[BATCH * HEADS * SEQ * HDIM];
__device__ __half g_Oh[MTOK * EMBED];

// ------------------------------- helpers -----------------------------------
__device__ __forceinline__ unsigned pk_f16(float f0, float f1) {
    unsigned d;
    asm("cvt.rn.f16x2.f32 %0, %1, %2;" : "=r"(d) : "f"(f1), "f"(f0));
    return d;
}
__device__ __forceinline__ void mma_f16(float* c, const unsigned* a, const unsigned* b) {
    asm volatile(
        "mma.sync.aligned.m16n8k16.row.col.f32.f16.f16.f32 "
        "{%0,%1,%2,%3}, {%4,%5,%6,%7}, {%8,%9}, {%0,%1,%2,%3};\n"
        : "+f"(c[0]), "+f"(c[1]), "+f"(c[2]), "+f"(c[3])
        : "r"(a[0]), "r"(a[1]), "r"(a[2]), "r"(a[3]),
          "r"(b[0]), "r"(b[1]));
}
__device__ __forceinline__ void ldsm_x4(unsigned& r0, unsigned& r1,
                                        unsigned& r2, unsigned& r3, unsigned addr) {
    asm volatile("ldmatrix.sync.aligned.m8n8.x4.shared.b16 {%0,%1,%2,%3}, [%4];"
                 : "=r"(r0), "=r"(r1), "=r"(r2), "=r"(r3) : "r"(addr));
}
__device__ __forceinline__ void ldsm_x4t(unsigned& r0, unsigned& r1,
                                         unsigned& r2, unsigned& r3, unsigned addr) {
    asm volatile("ldmatrix.sync.aligned.m8n8.x4.trans.shared.b16 {%0,%1,%2,%3}, [%4];"
                 : "=r"(r0), "=r"(r1), "=r"(r2), "=r"(r3) : "r"(addr));
}
__device__ __forceinline__ unsigned smem_u32(const void* p) {
    return (unsigned)__cvta_generic_to_shared(p);
}
#define CP_ASYNC16(dst, src) \
    asm volatile("cp.async.cg.shared.global [%0], [%1], 16;\n" :: "r"(dst), "l"(src))
#define CP_COMMIT() asm volatile("cp.async.commit_group;\n" ::: "memory")
#define CP_WAIT1()  asm volatile("cp.async.wait_group 1;\n" ::: "memory")

// ---------------------------------------------------------------------------
// Prep: fp32 -> fp16, vectorized (float4 -> 4 halves per thread).
// ---------------------------------------------------------------------------
__global__ __launch_bounds__(256)
void f2h_kernel(const float* __restrict__ src, __half* __restrict__ dst, int n4)
{
    const int i = blockIdx.x * blockDim.x + threadIdx.x;
    if (i < n4) {
        float4 v = ((const float4*)src)[i];
        ((uint2*)dst)[i] = make_uint2(pk_f16(v.x, v.y), pk_f16(v.z, v.w));
    }
}

// ---------------------------------------------------------------------------
// GEMM: C[M,N] = A[M,K] @ W[N,K]^T + bias[N], fp16 inputs.
// 128x128 tile, BK=64, 2-stage cp.async. 8 warps (4M x 2N), warp 32x64.
// Smem per stage: A tile 128x(128B data+16 pad) + B tile same = 36864 B.
// MODE 0: scatter fp16 Q(scaled)/K/V.  MODE 1: fp32 out + bias.
// ---------------------------------------------------------------------------
#define GSTG  18432                // one tile (128 rows x 144B)
#define GSMEM (2 * 2 * GSTG)       // 73728

template <int MODE>
__global__ __launch_bounds__(256, 2)
void gemm_h(const __half* __restrict__ A, const __half* __restrict__ W,
            const float* __restrict__ bias, float* __restrict__ out,
            int M, int N, int K)
{
    extern __shared__ char smg[];
    const unsigned sbase = smem_u32(smg);

    const int tid  = threadIdx.x;
    const int wid  = tid >> 5;
    const int lane = tid & 31;
    const int g    = lane >> 2;
    const int t    = lane & 3;

    const int wm0 = (wid & 3) * 32;
    const int wn0 = (wid >> 2) * 64;

    const int m0 = blockIdx.y * 128;
    const int n0 = blockIdx.x * 128;

    float acc[2][8][4];
#pragma unroll
    for (int mi = 0; mi < 2; ++mi)
#pragma unroll
        for (int nj = 0; nj < 8; ++nj)
#pragma unroll
            for (int r = 0; r < 4; ++r) acc[mi][nj][r] = 0.f;

    const int a_rsub = lane & 15;
    const int a_ko   = (lane >> 4) << 3;
    const int b_rs   = ((lane >> 4) << 3) + (lane & 7);
    const int b_ko   = ((lane >> 3) & 1) << 3;

    // Stage loader: A/B tiles 128 rows x 8 16B-chunks each; 8 cp.async/thread.
    auto load_stage = [&](int k0, int slot) {
        const unsigned st = sbase + slot * (2 * GSTG);
#pragma unroll
        for (int i = 0; i < 8; ++i) {
            const int idx = tid + 256 * i;      // 0..2047
            const int f   = idx & 1023;
            const int row = f >> 3;
            const int ch  = f & 7;
            const __half* src = (idx < 1024)
                ? &A[(size_t)(m0 + row) * K + k0 + ch * 8]
                : &W[(size_t)(n0 + row) * K + k0 + ch * 8];
            const unsigned dst = st + ((idx < 1024) ? 0 : GSTG) + row * 144 + ch * 16;
            CP_ASYNC16(dst, src);
        }
    };

    const int niter = K / 64;
    load_stage(0, 0); CP_COMMIT();

    for (int it = 0; it < niter; ++it) {
        if (it + 1 < niter) load_stage((it + 1) * 64, (it + 1) & 1);
        CP_COMMIT();
        CP_WAIT1();
        __syncthreads();                 // stage it resident; prior compute done

        const unsigned stA = sbase + (it & 1) * (2 * GSTG);
        const unsigned stB = stA + GSTG;
#pragma unroll
        for (int ks = 0; ks < 4; ++ks) {
            unsigned a[2][4];
#pragma unroll
            for (int mi = 0; mi < 2; ++mi) {
                const unsigned off =
                    (unsigned)((wm0 + mi * 16 + a_rsub) * 144 + (ks * 16 + a_ko) * 2);
                ldsm_x4(a[mi][0], a[mi][1], a[mi][2], a[mi][3], stA + off);
            }
#pragma unroll
            for (int njp = 0; njp < 4; ++njp) {
                const unsigned boff =
                    (unsigned)((wn0 + njp * 16 + b_rs) * 144 + (ks * 16 + b_ko) * 2);
                unsigned b[4];
                ldsm_x4(b[0], b[1], b[2], b[3], stB + boff);
#pragma unroll
                for (int mi = 0; mi < 2; ++mi) {
                    mma_f16(acc[mi][2 * njp],     a[mi], b + 0);
                    mma_f16(acc[mi][2 * njp + 1], a[mi], b + 2);
                }
            }
        }
        __syncthreads();                 // slot free for reload at it+2
    }

    // Epilogue. Pairs (c0,c1) and (c2,c3) are column-adjacent.
#pragma unroll
    for (int mi = 0; mi < 2; ++mi) {
#pragma unroll
        for (int nj = 0; nj < 8; ++nj) {
            const int n = n0 + wn0 + nj * 8 + 2 * t;
            const float b0 = bias[n], b1 = bias[n + 1];
#pragma unroll
            for (int half = 0; half < 2; ++half) {
                const int m = m0 + wm0 + mi * 16 + g + half * 8;
                float v0 = acc[mi][nj][2 * half]     + b0;
                float v1 = acc[mi][nj][2 * half + 1] + b1;
                if (MODE == 0) {
                    const int which = n >> 10;
                    const int rem   = n & 1023;
                    const int h     = rem >> 6;
                    const int dh    = rem & 63;          // even
                    const int b_    = m >> 11;
                    const int tkn   = m & 2047;
                    if (which == 0) { v0 *= SCALE; v1 *= SCALE; }
                    __half* dst = (which == 0) ? g_Qh : (which == 1) ? g_Kh : g_Vh;
                    *(unsigned*)&dst[(((size_t)(b_ * HEADS + h) * SEQ) + tkn) * HDIM + dh] =
                        pk_f16(v0, v1);
                } else {
                    *(float2*)&out[(size_t)m * N + n] = make_float2(v0, v1);
                }
            }
        }
    }
}

// ---------------------------------------------------------------------------
// Flash attention: fp16 S + PV (R13 math), cp.async double-buffered KV.
// 1 CTA per (bh, 128 q-rows); 8 warps x (16 q-rows x 64 kv). KV tile 64.
// Smem: QF [128][144B] 18432 | KV stages x2 (K 9216 + V 9216)  = 55296 B.
// ---------------------------------------------------------------------------
#define AQF   0
#define AKV   18432
#define AKVST 18432
#define SM_BYTES 55296
#define NKT (SEQ / 64)

__global__ __launch_bounds__(256, 2)
void flash_attn_mma()
{
    extern __shared__ char smc[];
    const unsigned sbase = smem_u32(smc);

    const int bh = blockIdx.y;
    const int q0 = blockIdx.x * 128;
    const __half* Qp = g_Qh + (size_t)bh * SEQ * HDIM;
    const __half* Kp = g_Kh + (size_t)bh * SEQ * HDIM;
    const __half* Vp = g_Vh + (size_t)bh * SEQ * HDIM;

    const int tid  = threadIdx.x;
    const int wid  = tid >> 5;
    const int lane = tid & 31;
    const int g    = lane >> 2;
    const int t    = lane & 3;
    const int arow = wid * 16;

    // KV stage loader: K tile 64x8 chunks + V tile 64x8 = 1024; 4/thread.
    auto kv_load = [&](int kt, int slot) {
        const unsigned st = sbase + AKV + slot * AKVST;
#pragma unroll
        for (int i = 0; i < 4; ++i) {
            const int idx = tid + 256 * i;      // 0..1023
            const int f   = idx & 511;
            const int row = f >> 3;
            const int ch  = f & 7;
            const __half* src = ((idx < 512) ? Kp : Vp)
                                + (size_t)(kt * 64 + row) * HDIM + ch * 8;
            const unsigned dst = st + ((idx < 512) ? 0 : 9216) + row * 144 + ch * 16;
            CP_ASYNC16(dst, src);
        }
    };

    kv_load(0, 0); CP_COMMIT();

    // Prologue: Q tile (already fp16 + pre-scaled) -> smem, plain copies.
#pragma unroll
    for (int i = 0; i < 4; ++i) {
        const int idx = tid + 256 * i;          // 0..1023 over 128 rows x 8 chunks
        const int r  = idx >> 3;
        const int ch = idx & 7;
        uint4 v = *(const uint4*)&Qp[(size_t)(q0 + r) * HDIM + ch * 8];
        *(uint4*)(smc + AQF + r * 144 + ch * 16) = v;
    }

    float o[8][4];
    float mrow[2] = {-1e30f, -1e30f};
    float lrow[2] = {0.f, 0.f};
#pragma unroll
    for (int nj = 0; nj < 8; ++nj)
#pragma unroll
        for (int r = 0; r < 4; ++r) o[nj][r] = 0.f;

    const unsigned FULL = 0xffffffffu;

    const int q_row = arow + (lane & 15);
    const int q_ko  = (lane >> 4) << 3;
    const int b_rs  = ((lane >> 4) << 3) + (lane & 7);
    const int b_ko  = ((lane >> 3) & 1) << 3;
    const int v_row = (((lane >> 3) & 1) << 3) + (lane & 7);
    const int v_co  = (lane >> 4) << 3;

    for (int kt = 0; kt < NKT; ++kt) {
        if (kt + 1 < NKT) kv_load(kt + 1, (kt + 1) & 1);
        CP_COMMIT();
        CP_WAIT1();
        __syncthreads();                 // stage kt resident; prior reads done

        const unsigned stK = sbase + AKV + (kt & 1) * AKVST;
        const unsigned stV = stK + 9216;

        // S = Q @ K^T (fp16).
        float s[8][4];
#pragma unroll
        for (int nj = 0; nj < 8; ++nj)
#pragma unroll
            for (int r = 0; r < 4; ++r) s[nj][r] = 0.f;

#pragma unroll
        for (int c16 = 0; c16 < 4; ++c16) {
            const unsigned qoff = (unsigned)(q_row * 144 + (c16 * 16 + q_ko) * 2);
            unsigned a[4];
            ldsm_x4(a[0], a[1], a[2], a[3], sbase + AQF + qoff);
#pragma unroll
            for (int njp = 0; njp < 4; ++njp) {
                const unsigned boff = (unsigned)((njp * 16 + b_rs) * 144
                                                 + (c16 * 16 + b_ko) * 2);
                unsigned b[4];
                ldsm_x4(b[0], b[1], b[2], b[3], stK + boff);
                mma_f16(s[2 * njp],     a, b + 0);
                mma_f16(s[2 * njp + 1], a, b + 2);
            }
        }

        // Online softmax (rows g and g+8).
#pragma unroll
        for (int h = 0; h < 2; ++h) {
            const int r0 = 2 * h;
            float mx = -1e30f;
#pragma unroll
            for (int nj = 0; nj < 8; ++nj)
                mx = fmaxf(mx, fmaxf(s[nj][r0], s[nj][r0 + 1]));
            mx = fmaxf(mx, __shfl_xor_sync(FULL, mx, 1));
            mx = fmaxf(mx, __shfl_xor_sync(FULL, mx, 2));
            const float mnew = fmaxf(mrow[h], mx);
            const float alpha = __expf(mrow[h] - mnew);
            float rs = 0.f;
#pragma unroll
            for (int nj = 0; nj < 8; ++nj) {
                s[nj][r0]     = __expf(s[nj][r0]     - mnew);
                s[nj][r0 + 1] = __expf(s[nj][r0 + 1] - mnew);
                rs += s[nj][r0] + s[nj][r0 + 1];
            }
            rs += __shfl_xor_sync(FULL, rs, 1);
            rs += __shfl_xor_sync(FULL, rs, 2);
            lrow[h] = alpha * lrow[h] + rs;
            mrow[h] = mnew;
#pragma unroll
            for (int nj = 0; nj < 8; ++nj) {
                o[nj][r0]     *= alpha;
                o[nj][r0 + 1] *= alpha;
            }
        }

        // O += P @ V, P fragments built from S fragments (fp16, registers).
#pragma unroll
        for (int c16 = 0; c16 < 4; ++c16) {
            unsigned ap[4];
            ap[0] = pk_f16(s[2 * c16][0],     s[2 * c16][1]);
            ap[1] = pk_f16(s[2 * c16][2],     s[2 * c16][3]);
            ap[2] = pk_f16(s[2 * c16 + 1][0], s[2 * c16 + 1][1]);
            ap[3] = pk_f16(s[2 * c16 + 1][2], s[2 * c16 + 1][3]);
            const unsigned vro = (unsigned)((c16 * 16 + v_row) * 144 + v_co * 2);
#pragma unroll
            for (int njp = 0; njp < 4; ++njp) {
                const unsigned voff = vro + (unsigned)(njp * 32);
                unsigned vb[4];
                ldsm_x4t(vb[0], vb[1], vb[2], vb[3], stV + voff);
                mma_f16(o[2 * njp],     ap, vb + 0);
                mma_f16(o[2 * njp + 1], ap, vb + 2);
            }
        }
        __syncthreads();                 // slot free for reload at kt+2
    }

    // Epilogue: normalize, write fp16 to g_Oh [B,N,EMBED].
    const int h  = bh & (HEADS - 1);
    const int b  = bh >> 4;
    const float inv0 = 1.0f / lrow[0];
    const float inv1 = 1.0f / lrow[1];
    const int r0 = q0 + arow + g;
#pragma unroll
    for (int nj = 0; nj < 8; ++nj) {
        const int col = h * HDIM + nj * 8 + 2 * t;
        *(unsigned*)&g_Oh[(size_t)(b * SEQ + r0) * EMBED + col] =
            pk_f16(o[nj][0] * inv0, o[nj][1] * inv0);
        *(unsigned*)&g_Oh[(size_t)(b * SEQ + r0 + 8) * EMBED + col] =
            pk_f16(o[nj][2] * inv1, o[nj][3] * inv1);
    }
}

// ---------------------------------------------------------------------------
extern "C" void kernel_launch(void* const* d_in, const int* in_sizes, int n_in,
                              void* d_out, int out_size)
{
    const float* x      = (const float*)d_in[0];
    const float* w_qkv  = (const float*)d_in[1];
    const float* b_qkv  = (const float*)d_in[2];
    const float* w_proj = (const float*)d_in[3];
    const float* b_proj = (const float*)d_in[4];
    float* out = (float*)d_out;

    __half *xh, *wqh, *wph, *oh;
    cudaGetSymbolAddress((void**)&xh,  g_xh);
    cudaGetSymbolAddress((void**)&wqh, g_wqh);
    cudaGetSymbolAddress((void**)&wph, g_wph);
    cudaGetSymbolAddress((void**)&oh,  g_Oh);

    static bool attr_set = false;
    if (!attr_set) {
        cudaFuncSetAttribute(gemm_h<0>,
                             cudaFuncAttributeMaxDynamicSharedMemorySize, GSMEM);
        cudaFuncSetAttribute(gemm_h<1>,
                             cudaFuncAttributeMaxDynamicSharedMemorySize, GSMEM);
        cudaFuncSetAttribute(flash_attn_mma,
                             cudaFuncAttributeMaxDynamicSharedMemorySize, SM_BYTES);
        attr_set = true;
    }

    // 0) fp32 -> fp16 prep
    f2h_kernel<<<(MTOK * EMBED / 4) / 256, 256>>>(x, xh, MTOK * EMBED / 4);
    f2h_kernel<<<(QKVN * EMBED / 4) / 256, 256>>>(w_qkv, wqh, QKVN * EMBED / 4);
    f2h_kernel<<<(EMBED * EMBED / 4) / 256, 256>>>(w_proj, wph, EMBED * EMBED / 4);

    // 1) QKV projection -> g_Qh (scaled) / g_Kh / g_Vh
    {
        dim3 grid(QKVN / 128, MTOK / 128);
        gemm_h<0><<<grid, 256, GSMEM>>>(xh, wqh, b_qkv, nullptr, MTOK, QKVN, EMBED);
    }
    // 2) Flash attention -> g_Oh
    {
        dim3 grid(SEQ / 128, BATCH * HEADS);
        flash_attn_mma<<<grid, 256, SM_BYTES>>>();
    }
    // 3) Output projection -> out (fp32)
    {
        dim3 grid(EMBED / 128, MTOK / 128);
        gemm_h<1><<<grid, 256, GSMEM>>>(oh, wph, b_proj, out, MTOK, EMBED, EMBED);
    }
}

// round 15
// speedup vs baseline: 2.8853x; 1.0291x over previous
#include <cuda_runtime.h>
#include <cuda_fp16.h>

// ---------------------------------------------------------------------------
// Fused MHA block, all-fp16 mma.sync, 3-stage cp.async pipelines:
//   prep      : x, w_qkv, w_proj -> fp16 (single fused launch)
//   QKV GEMM  : fp16 m16n8k16, BK=64, 3-stage, ONE barrier/iter
//   attention : fp16 S+PV, 3-stage KV pipeline, ONE barrier/iter
//   proj GEMM : fp16, 3-stage, fp32 out + bias
// Shapes: B=2, N=2048, EMBED=1024, HEADS=16, HDIM=64.
// ---------------------------------------------------------------------------

#define BATCH  2
#define SEQ    2048
#define EMBED  1024
#define HEADS  16
#define HDIM   64
#define MTOK   (BATCH * SEQ)      // 4096
#define QKVN   (3 * EMBED)        // 3072
#define SCALE  0.125f             // HDIM^-0.5

__device__ __half g_xh[MTOK * EMBED];
__device__ __half g_wqh[QKVN * EMBED];
__device__ __half g_wph[EMBED * EMBED];
__device__ __half g_Qh[BATCH * HEADS * SEQ * HDIM];   // pre-scaled by 0.125
__device__ __half g_Kh[BATCH * HEADS * SEQ * HDIM];
__device__ __half g_Vh[BATCH * HEADS * SEQ * HDIM];
__device__ __half g_Oh[MTOK * EMBED];

// ------------------------------- helpers -----------------------------------
__device__ __forceinline__ unsigned pk_f16(float f0, float f1) {
    unsigned d;
    asm("cvt.rn.f16x2.f32 %0, %1, %2;" : "=r"(d) : "f"(f1), "f"(f0));
    return d;
}
__device__ __forceinline__ void mma_f16(float* c, const unsigned* a, const unsigned* b) {
    asm volatile(
        "mma.sync.aligned.m16n8k16.row.col.f32.f16.f16.f32 "
        "{%0,%1,%2,%3}, {%4,%5,%6,%7}, {%8,%9}, {%0,%1,%2,%3};\n"
        : "+f"(c[0]), "+f"(c[1]), "+f"(c[2]), "+f"(c[3])
        : "r"(a[0]), "r"(a[1]), "r"(a[2]), "r"(a[3]),
          "r"(b[0]), "r"(b[1]));
}
__device__ __forceinline__ void ldsm_x4(unsigned& r0, unsigned& r1,
                                        unsigned& r2, unsigned& r3, unsigned addr) {
    asm volatile("ldmatrix.sync.aligned.m8n8.x4.shared.b16 {%0,%1,%2,%3}, [%4];"
                 : "=r"(r0), "=r"(r1), "=r"(r2), "=r"(r3) : "r"(addr));
}
__device__ __forceinline__ void ldsm_x4t(unsigned& r0, unsigned& r1,
                                         unsigned& r2, unsigned& r3, unsigned addr) {
    asm volatile("ldmatrix.sync.aligned.m8n8.x4.trans.shared.b16 {%0,%1,%2,%3}, [%4];"
                 : "=r"(r0), "=r"(r1), "=r"(r2), "=r"(r3) : "r"(addr));
}
__device__ __forceinline__ unsigned smem_u32(const void* p) {
    return (unsigned)__cvta_generic_to_shared(p);
}
#define CP_ASYNC16(dst, src) \
    asm volatile("cp.async.cg.shared.global [%0], [%1], 16;\n" :: "r"(dst), "l"(src))
#define CP_COMMIT() asm volatile("cp.async.commit_group;\n" ::: "memory")
#define CP_WAIT1()  asm volatile("cp.async.wait_group 1;\n" ::: "memory")

// ---------------------------------------------------------------------------
// Fused prep: convert x, w_qkv, w_proj to fp16 in one launch.
// ---------------------------------------------------------------------------
#define N4_X  (MTOK * EMBED / 4)       // 1048576
#define N4_WQ (QKVN * EMBED / 4)       // 786432
#define N4_WP (EMBED * EMBED / 4)      // 262144
#define N4_ALL (N4_X + N4_WQ + N4_WP)  // 2097152

__global__ __launch_bounds__(256)
void prep_kernel(const float* __restrict__ x, const float* __restrict__ wq,
                 const float* __restrict__ wp)
{
    const int i = blockIdx.x * blockDim.x + threadIdx.x;
    const float4* src;
    uint2* dst;
    int j = i;
    if (i < N4_X) {
        src = (const float4*)x;          dst = (uint2*)g_xh;
    } else if (i < N4_X + N4_WQ) {
        j = i - N4_X;
        src = (const float4*)wq;         dst = (uint2*)g_wqh;
    } else {
        j = i - N4_X - N4_WQ;
        src = (const float4*)wp;         dst = (uint2*)g_wph;
    }
    float4 v = src[j];
    dst[j] = make_uint2(pk_f16(v.x, v.y), pk_f16(v.z, v.w));
}

// ---------------------------------------------------------------------------
// GEMM: C[M,N] = A[M,K] @ W[N,K]^T + bias[N], fp16 inputs.
// 128x128 tile, BK=64, 3-stage cp.async, one barrier per iter.
// 8 warps (4M x 2N), warp 32x64. Stage = A tile 18432 + B tile 18432.
// MODE 0: scatter fp16 Q(scaled)/K/V.  MODE 1: fp32 out + bias.
// ---------------------------------------------------------------------------
#define GSTG  18432
#define GSMEM (3 * 2 * GSTG)       // 110592

template <int MODE>
__global__ __launch_bounds__(256, 2)
void gemm_h(const __half* __restrict__ A, const __half* __restrict__ W,
            const float* __restrict__ bias, float* __restrict__ out,
            int M, int N, int K)
{
    extern __shared__ char smg[];
    const unsigned sbase = smem_u32(smg);

    const int tid  = threadIdx.x;
    const int wid  = tid >> 5;
    const int lane = tid & 31;
    const int g    = lane >> 2;
    const int t    = lane & 3;

    const int wm0 = (wid & 3) * 32;
    const int wn0 = (wid >> 2) * 64;

    const int m0 = blockIdx.y * 128;
    const int n0 = blockIdx.x * 128;

    float acc[2][8][4];
#pragma unroll
    for (int mi = 0; mi < 2; ++mi)
#pragma unroll
        for (int nj = 0; nj < 8; ++nj)
#pragma unroll
            for (int r = 0; r < 4; ++r) acc[mi][nj][r] = 0.f;

    const int a_rsub = lane & 15;
    const int a_ko   = (lane >> 4) << 3;
    const int b_rs   = ((lane >> 4) << 3) + (lane & 7);
    const int b_ko   = ((lane >> 3) & 1) << 3;

    auto load_stage = [&](int k0, int slot) {
        const unsigned st = sbase + slot * (2 * GSTG);
#pragma unroll
        for (int i = 0; i < 8; ++i) {
            const int idx = tid + 256 * i;      // 0..2047
            const int f   = idx & 1023;
            const int row = f >> 3;
            const int ch  = f & 7;
            const __half* src = (idx < 1024)
                ? &A[(size_t)(m0 + row) * K + k0 + ch * 8]
                : &W[(size_t)(n0 + row) * K + k0 + ch * 8];
            const unsigned dst = st + ((idx < 1024) ? 0 : GSTG) + row * 144 + ch * 16;
            CP_ASYNC16(dst, src);
        }
    };

    const int niter = K / 64;
    load_stage(0, 0); CP_COMMIT();
    load_stage(64, 1); CP_COMMIT();

    for (int it = 0; it < niter; ++it) {
        CP_WAIT1();                      // stage it resident (it+1 may be pending)
        __syncthreads();                 // + all warps done with slot (it+2)%3
        if (it + 2 < niter) load_stage((it + 2) * 64, (it + 2) % 3);
        CP_COMMIT();                     // empty group at tail keeps numbering

        const unsigned stA = sbase + (it % 3) * (2 * GSTG);
        const unsigned stB = stA + GSTG;
#pragma unroll
        for (int ks = 0; ks < 4; ++ks) {
            unsigned a[2][4];
#pragma unroll
            for (int mi = 0; mi < 2; ++mi) {
                const unsigned off =
                    (unsigned)((wm0 + mi * 16 + a_rsub) * 144 + (ks * 16 + a_ko) * 2);
                ldsm_x4(a[mi][0], a[mi][1], a[mi][2], a[mi][3], stA + off);
            }
#pragma unroll
            for (int njp = 0; njp < 4; ++njp) {
                const unsigned boff =
                    (unsigned)((wn0 + njp * 16 + b_rs) * 144 + (ks * 16 + b_ko) * 2);
                unsigned b[4];
                ldsm_x4(b[0], b[1], b[2], b[3], stB + boff);
#pragma unroll
                for (int mi = 0; mi < 2; ++mi) {
                    mma_f16(acc[mi][2 * njp],     a[mi], b + 0);
                    mma_f16(acc[mi][2 * njp + 1], a[mi], b + 2);
                }
            }
        }
    }

    // Epilogue. Pairs (c0,c1) and (c2,c3) are column-adjacent.
#pragma unroll
    for (int mi = 0; mi < 2; ++mi) {
#pragma unroll
        for (int nj = 0; nj < 8; ++nj) {
            const int n = n0 + wn0 + nj * 8 + 2 * t;
            const float b0 = bias[n], b1 = bias[n + 1];
#pragma unroll
            for (int half = 0; half < 2; ++half) {
                const int m = m0 + wm0 + mi * 16 + g + half * 8;
                float v0 = acc[mi][nj][2 * half]     + b0;
                float v1 = acc[mi][nj][2 * half + 1] + b1;
                if (MODE == 0) {
                    const int which = n >> 10;
                    const int rem   = n & 1023;
                    const int h     = rem >> 6;
                    const int dh    = rem & 63;          // even
                    const int b_    = m >> 11;
                    const int tkn   = m & 2047;
                    if (which == 0) { v0 *= SCALE; v1 *= SCALE; }
                    __half* dst = (which == 0) ? g_Qh : (which == 1) ? g_Kh : g_Vh;
                    *(unsigned*)&dst[(((size_t)(b_ * HEADS + h) * SEQ) + tkn) * HDIM + dh] =
                        pk_f16(v0, v1);
                } else {
                    *(float2*)&out[(size_t)m * N + n] = make_float2(v0, v1);
                }
            }
        }
    }
}

// ---------------------------------------------------------------------------
// Flash attention: fp16 S + PV, 3-stage cp.async KV pipeline, one barrier/iter.
// 1 CTA per (bh, 128 q-rows); 8 warps x (16 q-rows x 64 kv). KV tile 64.
// Smem: QF [128][144B] 18432 | KV stages x3 (K 9216 + V 9216) = 73728 B.
// ---------------------------------------------------------------------------
#define AQF   0
#define AKV   18432
#define AKVST 18432
#define SM_BYTES (AKV + 3 * AKVST)    // 73728
#define NKT (SEQ / 64)

__global__ __launch_bounds__(256, 2)
void flash_attn_mma()
{
    extern __shared__ char smc[];
    const unsigned sbase = smem_u32(smc);

    const int bh = blockIdx.y;
    const int q0 = blockIdx.x * 128;
    const __half* Qp = g_Qh + (size_t)bh * SEQ * HDIM;
    const __half* Kp = g_Kh + (size_t)bh * SEQ * HDIM;
    const __half* Vp = g_Vh + (size_t)bh * SEQ * HDIM;

    const int tid  = threadIdx.x;
    const int wid  = tid >> 5;
    const int lane = tid & 31;
    const int g    = lane >> 2;
    const int t    = lane & 3;
    const int arow = wid * 16;

    auto kv_load = [&](int kt, int slot) {
        const unsigned st = sbase + AKV + slot * AKVST;
#pragma unroll
        for (int i = 0; i < 4; ++i) {
            const int idx = tid + 256 * i;      // 0..1023
            const int f   = idx & 511;
            const int row = f >> 3;
            const int ch  = f & 7;
            const __half* src = ((idx < 512) ? Kp : Vp)
                                + (size_t)(kt * 64 + row) * HDIM + ch * 8;
            const unsigned dst = st + ((idx < 512) ? 0 : 9216) + row * 144 + ch * 16;
            CP_ASYNC16(dst, src);
        }
    };

    kv_load(0, 0); CP_COMMIT();
    kv_load(1, 1); CP_COMMIT();

    // Prologue: Q tile (fp16, pre-scaled) -> smem, plain copies.
#pragma unroll
    for (int i = 0; i < 4; ++i) {
        const int idx = tid + 256 * i;          // 0..1023 over 128 rows x 8 chunks
        const int r  = idx >> 3;
        const int ch = idx & 7;
        uint4 v = *(const uint4*)&Qp[(size_t)(q0 + r) * HDIM + ch * 8];
        *(uint4*)(smc + AQF + r * 144 + ch * 16) = v;
    }

    float o[8][4];
    float mrow[2] = {-1e30f, -1e30f};
    float lrow[2] = {0.f, 0.f};
#pragma unroll
    for (int nj = 0; nj < 8; ++nj)
#pragma unroll
        for (int r = 0; r < 4; ++r) o[nj][r] = 0.f;

    const unsigned FULL = 0xffffffffu;

    const int q_row = arow + (lane & 15);
    const int q_ko  = (lane >> 4) << 3;
    const int b_rs  = ((lane >> 4) << 3) + (lane & 7);
    const int b_ko  = ((lane >> 3) & 1) << 3;
    const int v_row = (((lane >> 3) & 1) << 3) + (lane & 7);
    const int v_co  = (lane >> 4) << 3;

    for (int kt = 0; kt < NKT; ++kt) {
        CP_WAIT1();                      // stage kt resident
        __syncthreads();                 // + all warps done with slot (kt+2)%3
        if (kt + 2 < NKT) kv_load(kt + 2, (kt + 2) % 3);
        CP_COMMIT();                     // empty group at tail keeps numbering

        const unsigned stK = sbase + AKV + (kt % 3) * AKVST;
        const unsigned stV = stK + 9216;

        // S = Q @ K^T (fp16).
        float s[8][4];
#pragma unroll
        for (int nj = 0; nj < 8; ++nj)
#pragma unroll
            for (int r = 0; r < 4; ++r) s[nj][r] = 0.f;

#pragma unroll
        for (int c16 = 0; c16 < 4; ++c16) {
            const unsigned qoff = (unsigned)(q_row * 144 + (c16 * 16 + q_ko) * 2);
            unsigned a[4];
            ldsm_x4(a[0], a[1], a[2], a[3], sbase + AQF + qoff);
#pragma unroll
            for (int njp = 0; njp < 4; ++njp) {
                const unsigned boff = (unsigned)((njp * 16 + b_rs) * 144
                                                 + (c16 * 16 + b_ko) * 2);
                unsigned b[4];
                ldsm_x4(b[0], b[1], b[2], b[3], stK + boff);
                mma_f16(s[2 * njp],     a, b + 0);
                mma_f16(s[2 * njp + 1], a, b + 2);
            }
        }

        // Online softmax (rows g and g+8).
#pragma unroll
        for (int h = 0; h < 2; ++h) {
            const int r0 = 2 * h;
            float mx = -1e30f;
#pragma unroll
            for (int nj = 0; nj < 8; ++nj)
                mx = fmaxf(mx, fmaxf(s[nj][r0], s[nj][r0 + 1]));
            mx = fmaxf(mx, __shfl_xor_sync(FULL, mx, 1));
            mx = fmaxf(mx, __shfl_xor_sync(FULL, mx, 2));
            const float mnew = fmaxf(mrow[h], mx);
            const float alpha = __expf(mrow[h] - mnew);
            float rs = 0.f;
#pragma unroll
            for (int nj = 0; nj < 8; ++nj) {
                s[nj][r0]     = __expf(s[nj][r0]     - mnew);
                s[nj][r0 + 1] = __expf(s[nj][r0 + 1] - mnew);
                rs += s[nj][r0] + s[nj][r0 + 1];
            }
            rs += __shfl_xor_sync(FULL, rs, 1);
            rs += __shfl_xor_sync(FULL, rs, 2);
            lrow[h] = alpha * lrow[h] + rs;
            mrow[h] = mnew;
#pragma unroll
            for (int nj = 0; nj < 8; ++nj) {
                o[nj][r0]     *= alpha;
                o[nj][r0 + 1] *= alpha;
            }
        }

        // O += P @ V, P fragments built from S fragments (fp16, registers).
#pragma unroll
        for (int c16 = 0; c16 < 4; ++c16) {
            unsigned ap[4];
            ap[0] = pk_f16(s[2 * c16][0],     s[2 * c16][1]);
            ap[1] = pk_f16(s[2 * c16][2],     s[2 * c16][3]);
            ap[2] = pk_f16(s[2 * c16 + 1][0], s[2 * c16 + 1][1]);
            ap[3] = pk_f16(s[2 * c16 + 1][2], s[2 * c16 + 1][3]);
            const unsigned vro = (unsigned)((c16 * 16 + v_row) * 144 + v_co * 2);
#pragma unroll
            for (int njp = 0; njp < 4; ++njp) {
                const unsigned voff = vro + (unsigned)(njp * 32);
                unsigned vb[4];
                ldsm_x4t(vb[0], vb[1], vb[2], vb[3], stV + voff);
                mma_f16(o[2 * njp],     ap, vb + 0);
                mma_f16(o[2 * njp + 1], ap, vb + 2);
            }
        }
    }

    // Epilogue: normalize, write fp16 to g_Oh [B,N,EMBED].
    const int h  = bh & (HEADS - 1);
    const int b  = bh >> 4;
    const float inv0 = 1.0f / lrow[0];
    const float inv1 = 1.0f / lrow[1];
    const int r0 = q0 + arow + g;
#pragma unroll
    for (int nj = 0; nj < 8; ++nj) {
        const int col = h * HDIM + nj * 8 + 2 * t;
        *(unsigned*)&g_Oh[(size_t)(b * SEQ + r0) * EMBED + col] =
            pk_f16(o[nj][0] * inv0, o[nj][1] * inv0);
        *(unsigned*)&g_Oh[(size_t)(b * SEQ + r0 + 8) * EMBED + col] =
            pk_f16(o[nj][2] * inv1, o[nj][3] * inv1);
    }
}

// ---------------------------------------------------------------------------
extern "C" void kernel_launch(void* const* d_in, const int* in_sizes, int n_in,
                              void* d_out, int out_size)
{
    const float* x      = (const float*)d_in[0];
    const float* w_qkv  = (const float*)d_in[1];
    const float* b_qkv  = (const float*)d_in[2];
    const float* w_proj = (const float*)d_in[3];
    const float* b_proj = (const float*)d_in[4];
    float* out = (float*)d_out;

    __half *xh, *wqh, *wph, *oh;
    cudaGetSymbolAddress((void**)&xh,  g_xh);
    cudaGetSymbolAddress((void**)&wqh, g_wqh);
    cudaGetSymbolAddress((void**)&wph, g_wph);
    cudaGetSymbolAddress((void**)&oh,  g_Oh);

    static bool attr_set = false;
    if (!attr_set) {
        cudaFuncSetAttribute(gemm_h<0>,
                             cudaFuncAttributeMaxDynamicSharedMemorySize, GSMEM);
        cudaFuncSetAttribute(gemm_h<1>,
                             cudaFuncAttributeMaxDynamicSharedMemorySize, GSMEM);
        cudaFuncSetAttribute(flash_attn_mma,
                             cudaFuncAttributeMaxDynamicSharedMemorySize, SM_BYTES);
        attr_set = true;
    }

    // 0) fp32 -> fp16 prep (single fused launch)
    prep_kernel<<<N4_ALL / 256, 256>>>(x, w_qkv, w_proj);

    // 1) QKV projection -> g_Qh (scaled) / g_Kh / g_Vh
    {
        dim3 grid(QKVN / 128, MTOK / 128);
        gemm_h<0><<<grid, 256, GSMEM>>>(xh, wqh, b_qkv, nullptr, MTOK, QKVN, EMBED);
    }
    // 2) Flash attention -> g_Oh
    {
        dim3 grid(SEQ / 128, BATCH * HEADS);
        flash_attn_mma<<<grid, 256, SM_BYTES>>>();
    }
    // 3) Output projection -> out (fp32)
    {
        dim3 grid(EMBED / 128, MTOK / 128);
        gemm_h<1><<<grid, 256, GSMEM>>>(oh, wph, b_proj, out, MTOK, EMBED, EMBED);
    }
}

// round 16
// speedup vs baseline: 2.8988x; 1.0047x over previous
#include <cuda_runtime.h>
#include <cuda_fp16.h>

// ---------------------------------------------------------------------------
// Fused MHA block, all-fp16 mma.sync, ONE persistent kernel:
//   launch 1: prep (fp32->fp16 of x, w_qkv, w_proj) + counter reset
//   launch 2: persistent pull-queue kernel:
//       768 QKV tiles (column-major) -> 512 attention tiles -> 256 proj tiles
//       gated by per-column / per-(b,qblock) completion counters.
// Shapes: B=2, N=2048, EMBED=1024, HEADS=16, HDIM=64.
// ---------------------------------------------------------------------------

#define BATCH  2
#define SEQ    2048
#define EMBED  1024
#define HEADS  16
#define HDIM   64
#define MTOK   (BATCH * SEQ)      // 4096
#define QKVN   (3 * EMBED)        // 3072
#define SCALE  0.125f             // HDIM^-0.5

__device__ __half g_xh[MTOK * EMBED];
__device__ __half g_wqh[QKVN * EMBED];
__device__ __half g_wph[EMBED * EMBED];
__device__ __half g_Qh[BATCH * HEADS * SEQ * HDIM];   // pre-scaled by 0.125
__device__ __half g_Kh[BATCH * HEADS * SEQ * HDIM];
__device__ __half g_Vh[BATCH * HEADS * SEQ * HDIM];
__device__ __half g_Oh[MTOK * EMBED];

// Work queue + dependency counters (reset by prep each launch).
__device__ int g_ctr;
__device__ int g_qkv_cnt[24];     // per QKV n-column (128 wide): 32 m-blocks
__device__ int g_attn_cnt[32];    // per (b*16 + qblock): 16 heads

#define NQKV 768
#define NATT 512
#define NTOT 1536                 // 768 + 512 + 256

// ------------------------------- helpers -----------------------------------
__device__ __forceinline__ unsigned pk_f16(float f0, float f1) {
    unsigned d;
    asm("cvt.rn.f16x2.f32 %0, %1, %2;" : "=r"(d) : "f"(f1), "f"(f0));
    return d;
}
__device__ __forceinline__ void mma_f16(float* c, const unsigned* a, const unsigned* b) {
    asm volatile(
        "mma.sync.aligned.m16n8k16.row.col.f32.f16.f16.f32 "
        "{%0,%1,%2,%3}, {%4,%5,%6,%7}, {%8,%9}, {%0,%1,%2,%3};\n"
        : "+f"(c[0]), "+f"(c[1]), "+f"(c[2]), "+f"(c[3])
        : "r"(a[0]), "r"(a[1]), "r"(a[2]), "r"(a[3]),
          "r"(b[0]), "r"(b[1]));
}
__device__ __forceinline__ void ldsm_x4(unsigned& r0, unsigned& r1,
                                        unsigned& r2, unsigned& r3, unsigned addr) {
    asm volatile("ldmatrix.sync.aligned.m8n8.x4.shared.b16 {%0,%1,%2,%3}, [%4];"
                 : "=r"(r0), "=r"(r1), "=r"(r2), "=r"(r3) : "r"(addr));
}
__device__ __forceinline__ void ldsm_x4t(unsigned& r0, unsigned& r1,
                                         unsigned& r2, unsigned& r3, unsigned addr) {
    asm volatile("ldmatrix.sync.aligned.m8n8.x4.trans.shared.b16 {%0,%1,%2,%3}, [%4];"
                 : "=r"(r0), "=r"(r1), "=r"(r2), "=r"(r3) : "r"(addr));
}
__device__ __forceinline__ unsigned smem_u32(const void* p) {
    return (unsigned)__cvta_generic_to_shared(p);
}
#define CP_ASYNC16(dst, src) \
    asm volatile("cp.async.cg.shared.global [%0], [%1], 16;\n" :: "r"(dst), "l"(src))
#define CP_COMMIT() asm volatile("cp.async.commit_group;\n" ::: "memory")
#define CP_WAIT1()  asm volatile("cp.async.wait_group 1;\n" ::: "memory")

__device__ __forceinline__ void wait_cnt(volatile int* c, int target) {
    if (threadIdx.x == 0) { while (*c < target) { } }
    __syncthreads();
}

// ---------------------------------------------------------------------------
// Prep: fp32 -> fp16 for x/w_qkv/w_proj + reset queue/counters.
// ---------------------------------------------------------------------------
#define N4_X  (MTOK * EMBED / 4)
#define N4_WQ (QKVN * EMBED / 4)
#define N4_WP (EMBED * EMBED / 4)
#define N4_ALL (N4_X + N4_WQ + N4_WP)

__global__ __launch_bounds__(256)
void prep_kernel(const float* __restrict__ x, const float* __restrict__ wq,
                 const float* __restrict__ wp)
{
    if (blockIdx.x == 0) {
        const int tid = threadIdx.x;
        if (tid == 0) g_ctr = 0;
        if (tid < 24) g_qkv_cnt[tid] = 0;
        if (tid < 32) g_attn_cnt[tid] = 0;
    }
    const int i = blockIdx.x * blockDim.x + threadIdx.x;
    const float4* src;
    uint2* dst;
    int j = i;
    if (i < N4_X)                { src = (const float4*)x;  dst = (uint2*)g_xh; }
    else if (i < N4_X + N4_WQ)   { j = i - N4_X;  src = (const float4*)wq; dst = (uint2*)g_wqh; }
    else                         { j = i - N4_X - N4_WQ; src = (const float4*)wp; dst = (uint2*)g_wph; }
    float4 v = src[j];
    dst[j] = make_uint2(pk_f16(v.x, v.y), pk_f16(v.z, v.w));
}

// ---------------------------------------------------------------------------
// GEMM tile (fp16, BK=64, 3-stage cp.async). mode 0: QKV scatter, 1: proj out.
// ---------------------------------------------------------------------------
#define GSTG  18432
#define GSMEM (3 * 2 * GSTG)       // 110592 (fused kernel's smem size)

__device__ __forceinline__ void gemm_tile(
    const __half* __restrict__ A, const __half* __restrict__ W,
    const float* __restrict__ bias, float* __restrict__ out,
    int N, int m0, int n0, int mode, char* smg, unsigned sbase)
{
    const int K = EMBED;
    const int tid  = threadIdx.x;
    const int wid  = tid >> 5;
    const int lane = tid & 31;
    const int g    = lane >> 2;
    const int t    = lane & 3;
    const int wm0 = (wid & 3) * 32;
    const int wn0 = (wid >> 2) * 64;

    float acc[2][8][4];
#pragma unroll
    for (int mi = 0; mi < 2; ++mi)
#pragma unroll
        for (int nj = 0; nj < 8; ++nj)
#pragma unroll
            for (int r = 0; r < 4; ++r) acc[mi][nj][r] = 0.f;

    const int a_rsub = lane & 15;
    const int a_ko   = (lane >> 4) << 3;
    const int b_rs   = ((lane >> 4) << 3) + (lane & 7);
    const int b_ko   = ((lane >> 3) & 1) << 3;

    auto load_stage = [&](int k0, int slot) {
        const unsigned st = sbase + slot * (2 * GSTG);
#pragma unroll
        for (int i = 0; i < 8; ++i) {
            const int idx = tid + 256 * i;
            const int f   = idx & 1023;
            const int row = f >> 3;
            const int ch  = f & 7;
            const __half* src = (idx < 1024)
                ? &A[(size_t)(m0 + row) * K + k0 + ch * 8]
                : &W[(size_t)(n0 + row) * K + k0 + ch * 8];
            const unsigned dst = st + ((idx < 1024) ? 0 : GSTG) + row * 144 + ch * 16;
            CP_ASYNC16(dst, src);
        }
    };

    const int niter = K / 64;     // 16
    load_stage(0, 0); CP_COMMIT();
    load_stage(64, 1); CP_COMMIT();

    for (int it = 0; it < niter; ++it) {
        CP_WAIT1();
        __syncthreads();
        if (it + 2 < niter) load_stage((it + 2) * 64, (it + 2) % 3);
        CP_COMMIT();

        const unsigned stA = sbase + (it % 3) * (2 * GSTG);
        const unsigned stB = stA + GSTG;
#pragma unroll
        for (int ks = 0; ks < 4; ++ks) {
            unsigned a[2][4];
#pragma unroll
            for (int mi = 0; mi < 2; ++mi) {
                const unsigned off =
                    (unsigned)((wm0 + mi * 16 + a_rsub) * 144 + (ks * 16 + a_ko) * 2);
                ldsm_x4(a[mi][0], a[mi][1], a[mi][2], a[mi][3], stA + off);
            }
#pragma unroll
            for (int njp = 0; njp < 4; ++njp) {
                const unsigned boff =
                    (unsigned)((wn0 + njp * 16 + b_rs) * 144 + (ks * 16 + b_ko) * 2);
                unsigned b[4];
                ldsm_x4(b[0], b[1], b[2], b[3], stB + boff);
#pragma unroll
                for (int mi = 0; mi < 2; ++mi) {
                    mma_f16(acc[mi][2 * njp],     a[mi], b + 0);
                    mma_f16(acc[mi][2 * njp + 1], a[mi], b + 2);
                }
            }
        }
    }
    __syncthreads();               // smem quiescent before next queue item

    // Epilogue.
#pragma unroll
    for (int mi = 0; mi < 2; ++mi) {
#pragma unroll
        for (int nj = 0; nj < 8; ++nj) {
            const int n = n0 + wn0 + nj * 8 + 2 * t;
            const float b0 = bias[n], b1 = bias[n + 1];
#pragma unroll
            for (int half = 0; half < 2; ++half) {
                const int m = m0 + wm0 + mi * 16 + g + half * 8;
                float v0 = acc[mi][nj][2 * half]     + b0;
                float v1 = acc[mi][nj][2 * half + 1] + b1;
                if (mode == 0) {
                    const int which = n >> 10;
                    const int rem   = n & 1023;
                    const int h     = rem >> 6;
                    const int dh    = rem & 63;          // even
                    const int b_    = m >> 11;
                    const int tkn   = m & 2047;
                    if (which == 0) { v0 *= SCALE; v1 *= SCALE; }
                    __half* dst = (which == 0) ? g_Qh : (which == 1) ? g_Kh : g_Vh;
                    *(unsigned*)&dst[(((size_t)(b_ * HEADS + h) * SEQ) + tkn) * HDIM + dh] =
                        pk_f16(v0, v1);
                } else {
                    *(float2*)&out[(size_t)m * N + n] = make_float2(v0, v1);
                }
            }
        }
    }
}

// ---------------------------------------------------------------------------
// Attention tile: fp16 S + PV, 3-stage cp.async KV pipeline.
// ---------------------------------------------------------------------------
#define AQF   0
#define AKV   18432
#define AKVST 18432
#define NKT (SEQ / 64)

__device__ __forceinline__ void attn_tile(int qb, int bh, char* smc, unsigned sbase)
{
    const int q0 = qb * 128;
    const __half* Qp = g_Qh + (size_t)bh * SEQ * HDIM;
    const __half* Kp = g_Kh + (size_t)bh * SEQ * HDIM;
    const __half* Vp = g_Vh + (size_t)bh * SEQ * HDIM;

    const int tid  = threadIdx.x;
    const int wid  = tid >> 5;
    const int lane = tid & 31;
    const int g    = lane >> 2;
    const int t    = lane & 3;
    const int arow = wid * 16;

    auto kv_load = [&](int kt, int slot) {
        const unsigned st = sbase + AKV + slot * AKVST;
#pragma unroll
        for (int i = 0; i < 4; ++i) {
            const int idx = tid + 256 * i;
            const int f   = idx & 511;
            const int row = f >> 3;
            const int ch  = f & 7;
            const __half* src = ((idx < 512) ? Kp : Vp)
                                + (size_t)(kt * 64 + row) * HDIM + ch * 8;
            const unsigned dst = st + ((idx < 512) ? 0 : 9216) + row * 144 + ch * 16;
            CP_ASYNC16(dst, src);
        }
    };

    kv_load(0, 0); CP_COMMIT();
    kv_load(1, 1); CP_COMMIT();

#pragma unroll
    for (int i = 0; i < 4; ++i) {
        const int idx = tid + 256 * i;
        const int r  = idx >> 3;
        const int ch = idx & 7;
        uint4 v = *(const uint4*)&Qp[(size_t)(q0 + r) * HDIM + ch * 8];
        *(uint4*)(smc + AQF + r * 144 + ch * 16) = v;
    }

    float o[8][4];
    float mrow[2] = {-1e30f, -1e30f};
    float lrow[2] = {0.f, 0.f};
#pragma unroll
    for (int nj = 0; nj < 8; ++nj)
#pragma unroll
        for (int r = 0; r < 4; ++r) o[nj][r] = 0.f;

    const unsigned FULL = 0xffffffffu;
    const int q_row = arow + (lane & 15);
    const int q_ko  = (lane >> 4) << 3;
    const int b_rs  = ((lane >> 4) << 3) + (lane & 7);
    const int b_ko  = ((lane >> 3) & 1) << 3;
    const int v_row = (((lane >> 3) & 1) << 3) + (lane & 7);
    const int v_co  = (lane >> 4) << 3;

    for (int kt = 0; kt < NKT; ++kt) {
        CP_WAIT1();
        __syncthreads();
        if (kt + 2 < NKT) kv_load(kt + 2, (kt + 2) % 3);
        CP_COMMIT();

        const unsigned stK = sbase + AKV + (kt % 3) * AKVST;
        const unsigned stV = stK + 9216;

        float s[8][4];
#pragma unroll
        for (int nj = 0; nj < 8; ++nj)
#pragma unroll
            for (int r = 0; r < 4; ++r) s[nj][r] = 0.f;

#pragma unroll
        for (int c16 = 0; c16 < 4; ++c16) {
            const unsigned qoff = (unsigned)(q_row * 144 + (c16 * 16 + q_ko) * 2);
            unsigned a[4];
            ldsm_x4(a[0], a[1], a[2], a[3], sbase + AQF + qoff);
#pragma unroll
            for (int njp = 0; njp < 4; ++njp) {
                const unsigned boff = (unsigned)((njp * 16 + b_rs) * 144
                                                 + (c16 * 16 + b_ko) * 2);
                unsigned b[4];
                ldsm_x4(b[0], b[1], b[2], b[3], stK + boff);
                mma_f16(s[2 * njp],     a, b + 0);
                mma_f16(s[2 * njp + 1], a, b + 2);
            }
        }

#pragma unroll
        for (int h = 0; h < 2; ++h) {
            const int r0 = 2 * h;
            float mx = -1e30f;
#pragma unroll
            for (int nj = 0; nj < 8; ++nj)
                mx = fmaxf(mx, fmaxf(s[nj][r0], s[nj][r0 + 1]));
            mx = fmaxf(mx, __shfl_xor_sync(FULL, mx, 1));
            mx = fmaxf(mx, __shfl_xor_sync(FULL, mx, 2));
            const float mnew = fmaxf(mrow[h], mx);
            const float alpha = __expf(mrow[h] - mnew);
            float rs = 0.f;
#pragma unroll
            for (int nj = 0; nj < 8; ++nj) {
                s[nj][r0]     = __expf(s[nj][r0]     - mnew);
                s[nj][r0 + 1] = __expf(s[nj][r0 + 1] - mnew);
                rs += s[nj][r0] + s[nj][r0 + 1];
            }
            rs += __shfl_xor_sync(FULL, rs, 1);
            rs += __shfl_xor_sync(FULL, rs, 2);
            lrow[h] = alpha * lrow[h] + rs;
            mrow[h] = mnew;
            if (alpha != 1.0f) {           // bit-exact skip (x*1.0f == x)
#pragma unroll
                for (int nj = 0; nj < 8; ++nj) {
                    o[nj][r0]     *= alpha;
                    o[nj][r0 + 1] *= alpha;
                }
            }
        }

#pragma unroll
        for (int c16 = 0; c16 < 4; ++c16) {
            unsigned ap[4];
            ap[0] = pk_f16(s[2 * c16][0],     s[2 * c16][1]);
            ap[1] = pk_f16(s[2 * c16][2],     s[2 * c16][3]);
            ap[2] = pk_f16(s[2 * c16 + 1][0], s[2 * c16 + 1][1]);
            ap[3] = pk_f16(s[2 * c16 + 1][2], s[2 * c16 + 1][3]);
            const unsigned vro = (unsigned)((c16 * 16 + v_row) * 144 + v_co * 2);
#pragma unroll
            for (int njp = 0; njp < 4; ++njp) {
                const unsigned voff = vro + (unsigned)(njp * 32);
                unsigned vb[4];
                ldsm_x4t(vb[0], vb[1], vb[2], vb[3], stV + voff);
                mma_f16(o[2 * njp],     ap, vb + 0);
                mma_f16(o[2 * njp + 1], ap, vb + 2);
            }
        }
    }
    __syncthreads();               // smem quiescent before next queue item

    const int h  = bh & (HEADS - 1);
    const int b  = bh >> 4;
    const float inv0 = 1.0f / lrow[0];
    const float inv1 = 1.0f / lrow[1];
    const int r0 = q0 + arow + g;
#pragma unroll
    for (int nj = 0; nj < 8; ++nj) {
        const int col = h * HDIM + nj * 8 + 2 * t;
        *(unsigned*)&g_Oh[(size_t)(b * SEQ + r0) * EMBED + col] =
            pk_f16(o[nj][0] * inv0, o[nj][1] * inv0);
        *(unsigned*)&g_Oh[(size_t)(b * SEQ + r0 + 8) * EMBED + col] =
            pk_f16(o[nj][2] * inv1, o[nj][3] * inv1);
    }
}

// ---------------------------------------------------------------------------
// Persistent fused kernel: pull queue over 1536 tiles.
//   id <  768 : QKV tile, column-major (nb = id/32, mb = id%32)
//   id < 1280 : attn tile, qblock-major (qb = a/32, bh = a%32)
//   else      : proj tile (t = p/8 -> qb = t>>1, b = t&1; nb = p%8)
// ---------------------------------------------------------------------------
__global__ __launch_bounds__(256, 2)
void fused_kernel(const float* __restrict__ b_qkv,
                  const float* __restrict__ b_proj,
                  float* __restrict__ out)
{
    extern __shared__ char smc[];
    const unsigned sbase = smem_u32(smc);
    __shared__ int s_id;

    for (;;) {
        if (threadIdx.x == 0) s_id = atomicAdd(&g_ctr, 1);
        __syncthreads();
        const int id = s_id;
        __syncthreads();
        if (id >= NTOT) return;

        if (id < NQKV) {
            const int nb = id >> 5;           // 0..23
            const int mb = id & 31;           // 0..31
            gemm_tile(g_xh, g_wqh, b_qkv, nullptr, QKVN,
                      mb * 128, nb * 128, 0, smc, sbase);
            __threadfence();
            __syncthreads();
            if (threadIdx.x == 0) atomicAdd(&g_qkv_cnt[nb], 1);
        } else if (id < NQKV + NATT) {
            const int a  = id - NQKV;
            const int qb = a >> 5;            // 0..15
            const int bh = a & 31;            // 0..31
            const int c  = (bh & 15) >> 1;    // head pair column
            wait_cnt(&g_qkv_cnt[c], 32);          // Q column
            wait_cnt(&g_qkv_cnt[8 + c], 32);      // K column
            wait_cnt(&g_qkv_cnt[16 + c], 32);     // V column
            attn_tile(qb, bh, smc, sbase);
            __threadfence();
            __syncthreads();
            if (threadIdx.x == 0)
                atomicAdd(&g_attn_cnt[(bh >> 4) * 16 + qb], 1);
        } else {
            const int p  = id - NQKV - NATT;
            const int tt = p >> 3;            // 0..31
            const int nb = p & 7;             // 0..7
            const int qb = tt >> 1;
            const int b  = tt & 1;
            const int mb = b * 16 + qb;
            wait_cnt(&g_attn_cnt[mb], 16);
            gemm_tile(g_Oh, g_wph, b_proj, out, EMBED,
                      mb * 128, nb * 128, 1, smc, sbase);
        }
    }
}

// ---------------------------------------------------------------------------
extern "C" void kernel_launch(void* const* d_in, const int* in_sizes, int n_in,
                              void* d_out, int out_size)
{
    const float* x      = (const float*)d_in[0];
    const float* w_qkv  = (const float*)d_in[1];
    const float* b_qkv  = (const float*)d_in[2];
    const float* w_proj = (const float*)d_in[3];
    const float* b_proj = (const float*)d_in[4];
    float* out = (float*)d_out;

    static int n_sm = 0;
    if (n_sm == 0) {
        cudaDeviceGetAttribute(&n_sm, cudaDevAttrMultiProcessorCount, 0);
        cudaFuncSetAttribute(fused_kernel,
                             cudaFuncAttributeMaxDynamicSharedMemorySize, GSMEM);
    }

    // 0) prep: fp16 conversions + counter reset
    prep_kernel<<<N4_ALL / 256, 256>>>(x, w_qkv, w_proj);

    // 1) persistent fused QKV + attention + proj
    fused_kernel<<<n_sm * 2, 256, GSMEM>>>(b_qkv, b_proj, out);
}